// round 15
// baseline (speedup 1.0000x reference)
#include <cuda_runtime.h>
#include <cuda_fp16.h>
#include <math.h>
#include <stdint.h>

#define NTOK 4096      // B*T
#define DM   1024
#define NH   16
#define HD   64
#define NE   8
#define DFF  4096
#define NSLOT 8192     // NTOK * TOP_K
#define TT   1024
#define NBH  64        // B * NH

typedef __half h16;

// ===================== scratch (static device memory) ========================
__device__ h16    g_xn1_h [NTOK * DM];
__device__ h16    g_qh    [NTOK * DM];   // [B,H,T,HD] fp16, pre-scaled 0.125
__device__ h16    g_kh    [NTOK * DM];
__device__ h16    g_vh    [NTOK * DM];
__device__ h16    g_attn_h[NTOK * DM];
__device__ h16    g_xn2_h [NTOK * DM];
__device__ h16    g_hbuf  [(size_t)NSLOT * DFF];
__device__ float2 g_rope_tab[TT * 32];

// transposed weights ([N,K] K-major per expert)
__device__ h16 g_wqkvt_h[3 * DM * DM];
__device__ h16 g_wprojt_h[DM * DM];
__device__ h16 g_w1t[(size_t)NE * DFF * DM];
__device__ h16 g_w2t[(size_t)NE * DM * DFF];

__device__ int   g_cnt[NE];
__device__ int   g_off[NE];
__device__ int   g_cur[NE];
__device__ float g_probsum[NE];
__device__ int   g_top_i[NSLOT];
__device__ float g_top_w[NSLOT];
__device__ int   g_perm_tok[NSLOT];
__device__ float g_slot_gate[NSLOT];

__device__ __forceinline__ uint32_t smem_u32(const void* p) {
    uint32_t a;
    asm("{ .reg .u64 t; cvta.to.shared.u64 t, %1; cvt.u32.u64 %0, t; }"
        : "=r"(a) : "l"(p));
    return a;
}
__device__ __forceinline__ void ldsm4(uint32_t* r, uint32_t addr) {
    asm volatile("ldmatrix.sync.aligned.m8n8.x4.shared.b16 {%0,%1,%2,%3}, [%4];"
                 : "=r"(r[0]), "=r"(r[1]), "=r"(r[2]), "=r"(r[3]) : "r"(addr));
}
__device__ __forceinline__ void ldsm4t(uint32_t* r, uint32_t addr) {
    asm volatile("ldmatrix.sync.aligned.m8n8.x4.trans.shared.b16 {%0,%1,%2,%3}, [%4];"
                 : "=r"(r[0]), "=r"(r[1]), "=r"(r[2]), "=r"(r[3]) : "r"(addr));
}
__device__ __forceinline__ void mma_f16(float* d, const uint32_t* a, const uint32_t* b) {
    asm volatile(
        "mma.sync.aligned.m16n8k16.row.col.f32.f16.f16.f32 "
        "{%0,%1,%2,%3}, {%4,%5,%6,%7}, {%8,%9}, {%0,%1,%2,%3};"
        : "+f"(d[0]), "+f"(d[1]), "+f"(d[2]), "+f"(d[3])
        : "r"(a[0]), "r"(a[1]), "r"(a[2]), "r"(a[3]), "r"(b[0]), "r"(b[1]));
}
__device__ __forceinline__ void cp_async16(uint32_t saddr, const void* g, uint32_t sz) {
    asm volatile("cp.async.cg.shared.global [%0], [%1], 16, %2;"
                 :: "r"(saddr), "l"(g), "r"(sz));
}
__device__ __forceinline__ void cp_commit() {
    asm volatile("cp.async.commit_group;");
}
template<int N> __device__ __forceinline__ void cp_wait() {
    asm volatile("cp.async.wait_group %0;" :: "n"(N));
}
__device__ __forceinline__ uint32_t sw128(uint32_t o) {
    return o ^ ((o >> 3) & 0x70u);
}
__device__ __forceinline__ uint32_t h2pack(float a, float b) {
    half2 h = __floats2half2_rn(a, b);
    return *(uint32_t*)&h;
}

// ===================== small helpers ====================
__global__ void zero_small_kernel() {
    int i = threadIdx.x;
    if (i < NE) { g_cnt[i] = 0; g_cur[i] = 0; g_probsum[i] = 0.f; }
}

// rope sincos table: tab[t*32+f] = (cos, sin)(t * 10000^(-f/32))
__global__ void __launch_bounds__(256) rope_tab_kernel() {
    int idx = blockIdx.x * 256 + threadIdx.x;
    int t = idx >> 5, f = idx & 31;
    float freq = exp2f(-(float)f * 0.41524101186092029f);
    float sv, cv;
    __sincosf((float)t * freq, &sv, &cv);
    g_rope_tab[idx] = make_float2(cv, sv);
}

// ---------------- transpose + convert: w[K,N] -> t[N,K] ----------------------
__global__ void __launch_bounds__(256) trans_conv(
    const float* __restrict__ w, h16* __restrict__ th, int K, int N)
{
    const size_t eoff = (size_t)blockIdx.z * K * N;
    const float* wp = w + eoff;
    h16* thp = th + eoff;
    __shared__ float t[32][33];
    int tx = threadIdx.x & 31, ty = threadIdx.x >> 5;
    int n0 = blockIdx.x * 32, k0 = blockIdx.y * 32;
    #pragma unroll
    for (int i = 0; i < 4; i++)
        t[ty + i * 8][tx] = wp[(size_t)(k0 + ty + i * 8) * N + n0 + tx];
    __syncthreads();
    #pragma unroll
    for (int i = 0; i < 4; i++) {
        float v = t[tx][ty + i * 8];
        int n = n0 + ty + i * 8, k = k0 + tx;
        thp[(size_t)n * K + k] = __float2half_rn(v);
    }
}

// ---------------- layernorm (256 thr/row) ----------------
__global__ void __launch_bounds__(256) ln_kernel(
    const float* __restrict__ x, const float* __restrict__ g,
    const float* __restrict__ b, h16* __restrict__ oh)
{
    int row = blockIdx.x;
    const float* xr = x + (size_t)row * DM;
    float v[4]; float s = 0.f, ss = 0.f;
    #pragma unroll
    for (int i = 0; i < 4; i++) {
        float u = xr[threadIdx.x + i * 256];
        v[i] = u; s += u; ss += u * u;
    }
    #pragma unroll
    for (int ofs = 16; ofs > 0; ofs >>= 1) {
        s  += __shfl_xor_sync(0xffffffffu, s,  ofs);
        ss += __shfl_xor_sync(0xffffffffu, ss, ofs);
    }
    __shared__ float sh[2][8];
    int warp = threadIdx.x >> 5, lane = threadIdx.x & 31;
    if (lane == 0) { sh[0][warp] = s; sh[1][warp] = ss; }
    __syncthreads();
    float S = 0.f, SS = 0.f;
    #pragma unroll
    for (int w = 0; w < 8; w++) { S += sh[0][w]; SS += sh[1][w]; }
    float mu  = S * (1.0f / DM);
    float var = SS * (1.0f / DM) - mu * mu;
    float inv = rsqrtf(var + 1e-5f);
    #pragma unroll
    for (int i = 0; i < 4; i++) {
        int idx = threadIdx.x + i * 256;
        float o = (v[i] - mu) * inv * g[idx] + b[idx];
        oh[(size_t)row * DM + idx] = __float2half_rn(o);
    }
}

// ---------------- fused ln2 + router (reads x2 from out) ---------------------
__global__ void __launch_bounds__(256) ln2_router_kernel(
    const float* __restrict__ x, const float* __restrict__ g,
    const float* __restrict__ b, h16* __restrict__ oh,
    const float* __restrict__ wr)
{
    int row = blockIdx.x, tid = threadIdx.x;
    const float* xr = x + (size_t)row * DM;
    float v[4]; float s = 0.f, ss = 0.f;
    #pragma unroll
    for (int i = 0; i < 4; i++) {
        float u = xr[tid + i * 256];
        v[i] = u; s += u; ss += u * u;
    }
    #pragma unroll
    for (int ofs = 16; ofs > 0; ofs >>= 1) {
        s  += __shfl_xor_sync(0xffffffffu, s,  ofs);
        ss += __shfl_xor_sync(0xffffffffu, ss, ofs);
    }
    __shared__ float sh[2][8];
    int warp = tid >> 5, lane = tid & 31;
    if (lane == 0) { sh[0][warp] = s; sh[1][warp] = ss; }
    __syncthreads();
    float S = 0.f, SS = 0.f;
    #pragma unroll
    for (int w = 0; w < 8; w++) { S += sh[0][w]; SS += sh[1][w]; }
    float mu  = S * (1.0f / DM);
    float var = SS * (1.0f / DM) - mu * mu;
    float inv = rsqrtf(var + 1e-5f);
    float pe[NE];
    #pragma unroll
    for (int e = 0; e < NE; e++) pe[e] = 0.f;
    #pragma unroll
    for (int i = 0; i < 4; i++) {
        int idx = tid + i * 256;
        float o = (v[i] - mu) * inv * g[idx] + b[idx];
        oh[(size_t)row * DM + idx] = __float2half_rn(o);
        const float* w = wr + idx * NE;
        #pragma unroll
        for (int e = 0; e < NE; e++) pe[e] += o * w[e];
    }
    __shared__ float red[NE][256];
    #pragma unroll
    for (int e = 0; e < NE; e++) red[e][tid] = pe[e];
    __syncthreads();
    for (int st = 128; st > 0; st >>= 1) {
        if (tid < st) {
            #pragma unroll
            for (int e = 0; e < NE; e++) red[e][tid] += red[e][tid + st];
        }
        __syncthreads();
    }
    if (tid == 0) {
        float lg[NE], mx = -1e30f;
        #pragma unroll
        for (int e = 0; e < NE; e++) { lg[e] = red[e][0]; mx = fmaxf(mx, lg[e]); }
        float se = 0.f, pr[NE];
        #pragma unroll
        for (int e = 0; e < NE; e++) { pr[e] = __expf(lg[e] - mx); se += pr[e]; }
        float invs = 1.0f / se;
        #pragma unroll
        for (int e = 0; e < NE; e++) {
            pr[e] *= invs;
            atomicAdd(&g_probsum[e], pr[e]);
        }
        int i0 = 0;
        #pragma unroll
        for (int e = 1; e < NE; e++) if (pr[e] > pr[i0]) i0 = e;
        int i1 = (i0 == 0) ? 1 : 0;
        #pragma unroll
        for (int e = 0; e < NE; e++) if (e != i0 && pr[e] > pr[i1]) i1 = e;
        float w0 = pr[i0], w1 = pr[i1], sw = 1.0f / (w0 + w1);
        g_top_i[row * 2] = i0; g_top_i[row * 2 + 1] = i1;
        g_top_w[row * 2] = w0 * sw; g_top_w[row * 2 + 1] = w1 * sw;
        atomicAdd(&g_cnt[i0], 1);
        atomicAdd(&g_cnt[i1], 1);
    }
}

// ---------------- tensor-core flash attention --------------------------------
#define ATTN_SMEM 49152
__global__ void __launch_bounds__(256, 2) attn_kernel(
    const h16* __restrict__ q, const h16* __restrict__ k,
    const h16* __restrict__ v, h16* __restrict__ oh)
{
    extern __shared__ char smem[];
    uint32_t sb = smem_u32(smem);
    const uint32_t SQ = 0, SKV = 16384, STG = 16384;

    int bh = blockIdx.x & (NBH - 1);
    int chunk = (TT / 128 - 1) - (blockIdx.x >> 6);
    int qb0 = chunk * 128;
    int tid = threadIdx.x, lane = tid & 31, w = tid >> 5;
    const h16* qb = q + (size_t)bh * TT * HD;
    const h16* kb = k + (size_t)bh * TT * HD;
    const h16* vb = v + (size_t)bh * TT * HD;

    for (int i = tid; i < 128 * 8; i += 256) {
        int r = i >> 3, ch = i & 7;
        uint32_t so = sw128((uint32_t)(r * 128 + ch * 16));
        *(uint4*)(smem + SQ + so) = *(const uint4*)(qb + (size_t)(qb0 + r) * HD + ch * 8);
    }

    auto load_kv = [&](int j0, int st) {
        uint32_t s0 = sb + SKV + (uint32_t)st * STG;
        #pragma unroll
        for (int i = 0; i < 2; i++) {
            int idx = tid + i * 256;
            int r = idx >> 3, ch = idx & 7;
            uint32_t so = sw128((uint32_t)(r * 128 + ch * 16));
            cp_async16(s0 + so, kb + (size_t)(j0 + r) * HD + ch * 8, 16);
            cp_async16(s0 + 8192 + so, vb + (size_t)(j0 + r) * HD + ch * 8, 16);
        }
        cp_commit();
    };
    load_kv(0, 0);
    __syncthreads();

    uint32_t qf[4][4];
    #pragma unroll
    for (int ks = 0; ks < 4; ks++) {
        int row = w * 16 + (lane & 15);
        uint32_t so = sw128((uint32_t)(row * 128 + ks * 32 + (lane >> 4) * 16));
        ldsm4(qf[ks], sb + SQ + so);
    }

    float oacc[8][4];
    #pragma unroll
    for (int i = 0; i < 8; i++)
        #pragma unroll
        for (int j = 0; j < 4; j++) oacc[i][j] = 0.f;
    float mrun[2] = {-1e30f, -1e30f}, lsum[2] = {0.f, 0.f};

    const int wrow = qb0 + w * 16 + (lane >> 2);
    const int wt_last = qb0 + w * 16 + 15;
    const int wt_first = qb0 + w * 16;
    const int ntiles = (qb0 + 128) / 64;

    for (int ti = 0; ti < ntiles; ti++) {
        int j0 = ti * 64;
        if (ti + 1 < ntiles) { load_kv(j0 + 64, (ti + 1) & 1); cp_wait<1>(); }
        else cp_wait<0>();
        __syncthreads();
        if (j0 <= wt_last) {
            uint32_t s0 = sb + SKV + (uint32_t)(ti & 1) * STG;
            float sacc[8][4];
            #pragma unroll
            for (int i = 0; i < 8; i++)
                #pragma unroll
                for (int j = 0; j < 4; j++) sacc[i][j] = 0.f;
            #pragma unroll
            for (int ks = 0; ks < 4; ks++) {
                #pragma unroll
                for (int n2 = 0; n2 < 4; n2++) {
                    int row = n2 * 16 + (lane & 15);
                    uint32_t so = sw128((uint32_t)(row * 128 + ks * 32 + (lane >> 4) * 16));
                    uint32_t t4[4]; ldsm4(t4, s0 + so);
                    uint32_t b0[2] = {t4[0], t4[2]}, b1[2] = {t4[1], t4[3]};
                    mma_f16(sacc[2 * n2], qf[ks], b0);
                    mma_f16(sacc[2 * n2 + 1], qf[ks], b1);
                }
            }
            if (j0 + 63 > wt_first) {
                #pragma unroll
                for (int nt = 0; nt < 8; nt++)
                    #pragma unroll
                    for (int r = 0; r < 4; r++) {
                        int col = j0 + 8 * nt + 2 * (lane & 3) + (r & 1);
                        int rowt = wrow + 8 * (r >> 1);
                        if (col > rowt) sacc[nt][r] = -1e30f;
                    }
            }
            float psc[2];
            #pragma unroll
            for (int hh = 0; hh < 2; hh++) {
                float mx = -1e30f;
                #pragma unroll
                for (int nt = 0; nt < 8; nt++) {
                    mx = fmaxf(mx, sacc[nt][2 * hh]);
                    mx = fmaxf(mx, sacc[nt][2 * hh + 1]);
                }
                mx = fmaxf(mx, __shfl_xor_sync(0xffffffffu, mx, 1));
                mx = fmaxf(mx, __shfl_xor_sync(0xffffffffu, mx, 2));
                float nm = fmaxf(mrun[hh], mx);
                float sc = __expf(mrun[hh] - nm);
                mrun[hh] = nm;
                float sum = 0.f;
                #pragma unroll
                for (int nt = 0; nt < 8; nt++) {
                    float p0 = __expf(sacc[nt][2 * hh] - nm);
                    float p1 = __expf(sacc[nt][2 * hh + 1] - nm);
                    sacc[nt][2 * hh] = p0; sacc[nt][2 * hh + 1] = p1;
                    sum += p0 + p1;
                }
                sum += __shfl_xor_sync(0xffffffffu, sum, 1);
                sum += __shfl_xor_sync(0xffffffffu, sum, 2);
                lsum[hh] = lsum[hh] * sc + sum;
                psc[hh] = sc;
            }
            #pragma unroll
            for (int nt = 0; nt < 8; nt++)
                #pragma unroll
                for (int r = 0; r < 4; r++)
                    oacc[nt][r] *= psc[r >> 1];
            uint32_t pf[4][4];
            #pragma unroll
            for (int kt = 0; kt < 4; kt++) {
                pf[kt][0] = h2pack(sacc[2 * kt][0], sacc[2 * kt][1]);
                pf[kt][1] = h2pack(sacc[2 * kt][2], sacc[2 * kt][3]);
                pf[kt][2] = h2pack(sacc[2 * kt + 1][0], sacc[2 * kt + 1][1]);
                pf[kt][3] = h2pack(sacc[2 * kt + 1][2], sacc[2 * kt + 1][3]);
            }
            uint32_t sv = s0 + 8192;
            int g = lane >> 3, rr = lane & 7;
            #pragma unroll
            for (int dp = 0; dp < 4; dp++) {
                #pragma unroll
                for (int kt = 0; kt < 4; kt++) {
                    int kvr = 16 * kt + 8 * (g & 1) + rr;
                    int dc = dp * 16 + 8 * (g >> 1);
                    uint32_t so = sw128((uint32_t)(kvr * 128 + dc * 2));
                    uint32_t t4[4]; ldsm4t(t4, sv + so);
                    uint32_t b0[2] = {t4[0], t4[1]}, b1[2] = {t4[2], t4[3]};
                    mma_f16(oacc[2 * dp], pf[kt], b0);
                    mma_f16(oacc[2 * dp + 1], pf[kt], b1);
                }
            }
        }
        __syncthreads();
    }
    int b = bh >> 4, hH = bh & 15;
    #pragma unroll
    for (int hh = 0; hh < 2; hh++) {
        float inv = 1.0f / lsum[hh];
        int t = wrow + 8 * hh;
        size_t op = ((size_t)(b * TT + t)) * DM + hH * HD;
        #pragma unroll
        for (int nt = 0; nt < 8; nt++) {
            int d = 8 * nt + 2 * (lane & 3);
            half2 hv = __floats2half2_rn(oacc[nt][2 * hh] * inv, oacc[nt][2 * hh + 1] * inv);
            *(half2*)(oh + op + d) = hv;
        }
    }
}

// ===================== 128x256 HMMA GEMM core (4-stage, occ 1) ===============
#define NSTG 4
__device__ __forceinline__ void gemm256(
    uint32_t sb, float (*acc)[4],
    const h16* __restrict__ A, const h16* __restrict__ B,
    int K, const int* __restrict__ perm, int row_base, int valid, int n0)
{
    constexpr uint32_t T_B = 16384;
    constexpr uint32_t STAGE = 49152;
    const int tid = threadIdx.x, lane = tid & 31, wid = tid >> 5;
    const int wm = wid >> 2, wn = wid & 3;
    const int nkb = K >> 6;

    const int arow = tid >> 3, ach = tid & 7;
    uint32_t asz[4];
    size_t aoff[4];
    #pragma unroll
    for (int it = 0; it < 4; it++) {
        int row = arow + it * 32;
        asz[it] = (row < valid) ? 16u : 0u;
        int gra = (row < valid) ? (perm ? perm[row_base + row] : (row_base + row)) : 0;
        aoff[it] = (size_t)gra * K;
    }

    auto load_stage = [&](int kb) {
        uint32_t s0 = sb + (uint32_t)(kb & (NSTG - 1)) * STAGE;
        int koff = kb * 64 + ach * 8;
        #pragma unroll
        for (int it = 0; it < 4; it++) {
            int row = arow + it * 32;
            uint32_t so = sw128((uint32_t)(row * 128 + ach * 16));
            cp_async16(s0 + so, A + aoff[it] + koff, asz[it]);
        }
        #pragma unroll
        for (int it = 0; it < 8; it++) {
            int row = arow + it * 32;
            uint32_t so = sw128((uint32_t)(row * 128 + ach * 16));
            cp_async16(s0 + T_B + so, B + (size_t)(n0 + row) * K + koff, 16u);
        }
        cp_commit();
    };

    #pragma unroll
    for (int s = 0; s < NSTG - 1; s++)
        if (s < nkb) load_stage(s);

    for (int kb = 0; kb < nkb; kb++) {
        if (kb + NSTG - 1 < nkb) { load_stage(kb + NSTG - 1); cp_wait<NSTG - 1>(); }
        else {
            int rem = nkb - 1 - kb;
            if (rem >= 2) cp_wait<2>();
            else if (rem == 1) cp_wait<1>();
            else cp_wait<0>();
        }
        __syncthreads();
        uint32_t s0 = sb + (uint32_t)(kb & (NSTG - 1)) * STAGE;
        #pragma unroll
        for (int ks = 0; ks < 4; ks++) {
            uint32_t af[4][4];
            #pragma unroll
            for (int mt = 0; mt < 4; mt++) {
                int row = wm * 64 + mt * 16 + (lane & 15);
                uint32_t so = sw128((uint32_t)(row * 128 + ks * 32 + (lane >> 4) * 16));
                ldsm4(af[mt], s0 + so);
            }
            uint32_t bf[8][2];
            #pragma unroll
            for (int n2 = 0; n2 < 4; n2++) {
                int row = wn * 64 + n2 * 16 + (lane & 15);
                uint32_t so = sw128((uint32_t)(row * 128 + ks * 32 + (lane >> 4) * 16));
                uint32_t t4[4];
                ldsm4(t4, s0 + T_B + so);
                bf[n2 * 2][0] = t4[0]; bf[n2 * 2][1] = t4[2];
                bf[n2 * 2 + 1][0] = t4[1]; bf[n2 * 2 + 1][1] = t4[3];
            }
            #pragma unroll
            for (int mt = 0; mt < 4; mt++)
                #pragma unroll
                for (int nt = 0; nt < 8; nt++)
                    mma_f16(acc[mt * 8 + nt], af[mt], bf[nt]);
        }
        __syncthreads();
    }
}
// acc[mt*8+nt][r]: row = wm*64 + mt*16 + lane/4 + 8*(r>>1)
//                  col = wn*64 + nt*8  + 2*(lane&3) + (r&1)

#define GEMM_SMEM 196608
#define ACC_INIT float acc[32][4]; \
    _Pragma("unroll") for (int i = 0; i < 32; i++) \
    _Pragma("unroll") for (int j = 0; j < 4; j++) acc[i][j] = 0.f;

// ---------------- qkv gemm + fused rope -> fp16 q/k/v ------------------------
__global__ void __launch_bounds__(256, 1) qkv_gemm() {
    extern __shared__ char smem[];
    uint32_t sb = smem_u32(smem);
    ACC_INIT
    int m0 = blockIdx.y * 128, n0 = blockIdx.x * 256;
    gemm256(sb, acc, g_xn1_h, g_wqkvt_h, DM, nullptr, m0, 128, n0);
    int lane = threadIdx.x & 31, wid = threadIdx.x >> 5;
    int wm = wid >> 2, wn = wid & 3;
    int c_base = n0 + wn * 64;
    int sec = c_base >> 10;             // 0=q, 1=k, 2=v
    int h = (c_base & 1023) >> 6;       // head index
    h16* dstq = (sec == 0) ? g_qh : g_kh;
    #pragma unroll
    for (int mt = 0; mt < 4; mt++) {
        #pragma unroll
        for (int half = 0; half < 2; half++) {
            int rg = m0 + wm * 64 + mt * 16 + (lane >> 2) + half * 8;
            int t = rg & (TT - 1), bb = rg >> 10;
            size_t dbase = ((size_t)((bb * NH + h) * TT) + t) * HD;
            #pragma unroll
            for (int nt = 0; nt < 4; nt++) {
                int d = nt * 8 + 2 * (lane & 3);
                float a0 = acc[mt * 8 + nt][half * 2];
                float a1 = acc[mt * 8 + nt][half * 2 + 1];
                float b0 = acc[mt * 8 + nt + 4][half * 2];
                float b1 = acc[mt * 8 + nt + 4][half * 2 + 1];
                if (sec == 2) {
                    *(half2*)(g_vh + dbase + d)      = __floats2half2_rn(a0, a1);
                    *(half2*)(g_vh + dbase + d + 32) = __floats2half2_rn(b0, b1);
                } else {
                    float2 cs0 = g_rope_tab[t * 32 + d];
                    float2 cs1 = g_rope_tab[t * 32 + d + 1];
                    float lo0 = a0 * cs0.x - b0 * cs0.y;
                    float lo1 = a1 * cs1.x - b1 * cs1.y;
                    float hi0 = b0 * cs0.x + a0 * cs0.y;
                    float hi1 = b1 * cs1.x + a1 * cs1.y;
                    if (sec == 0) { lo0 *= 0.125f; lo1 *= 0.125f; hi0 *= 0.125f; hi1 *= 0.125f; }
                    *(half2*)(dstq + dbase + d)      = __floats2half2_rn(lo0, lo1);
                    *(half2*)(dstq + dbase + d + 32) = __floats2half2_rn(hi0, hi1);
                }
            }
        }
    }
}

// ---------------- x2 = attn @ w_proj + b_proj + x -> out ---------------------
__global__ void __launch_bounds__(256, 1) proj_gemm(
    const float* __restrict__ bias, const float* __restrict__ resid,
    float* __restrict__ out)
{
    extern __shared__ char smem[];
    uint32_t sb = smem_u32(smem);
    ACC_INIT
    int m0 = blockIdx.y * 128, n0 = blockIdx.x * 256;
    gemm256(sb, acc, g_attn_h, g_wprojt_h, DM, nullptr, m0, 128, n0);
    int lane = threadIdx.x & 31, wid = threadIdx.x >> 5;
    int wm = wid >> 2, wn = wid & 3;
    #pragma unroll
    for (int mt = 0; mt < 4; mt++)
        #pragma unroll
        for (int nt = 0; nt < 8; nt++) {
            int r = m0 + wm * 64 + mt * 16 + (lane >> 2);
            int c = n0 + wn * 64 + nt * 8 + 2 * (lane & 3);
            float* d = acc[mt * 8 + nt];
            size_t p0 = (size_t)r * DM + c;
            size_t p1 = (size_t)(r + 8) * DM + c;
            out[p0]     = d[0] + bias[c]     + resid[p0];
            out[p0 + 1] = d[1] + bias[c + 1] + resid[p0 + 1];
            out[p1]     = d[2] + bias[c]     + resid[p1];
            out[p1 + 1] = d[3] + bias[c + 1] + resid[p1 + 1];
        }
}

// ---------------- h = gelu(gather(xn2) @ w1[e] + b1[e])  (per-expert) --------
__global__ void __launch_bounds__(256, 1) ffn1_gemm(int e, const float* __restrict__ B1) {
    int cnt = g_cnt[e];
    int r0 = blockIdx.y * 128;
    if (r0 >= cnt) return;
    extern __shared__ char smem[];
    uint32_t sb = smem_u32(smem);
    ACC_INIT
    int off = g_off[e];
    int n0 = blockIdx.x * 256;
    int valid = cnt - r0; if (valid > 128) valid = 128;
    gemm256(sb, acc, g_xn2_h, g_w1t + (size_t)e * DFF * DM,
            DM, g_perm_tok, off + r0, valid, n0);
    int lane = threadIdx.x & 31, wid = threadIdx.x >> 5;
    int wm = wid >> 2, wn = wid & 3;
    const float* bias = B1 + e * DFF;
    #pragma unroll
    for (int mt = 0; mt < 4; mt++)
        #pragma unroll
        for (int nt = 0; nt < 8; nt++) {
            int rl = wm * 64 + mt * 16 + (lane >> 2);
            int c = n0 + wn * 64 + nt * 8 + 2 * (lane & 3);
            float* d = acc[mt * 8 + nt];
            #pragma unroll
            for (int half = 0; half < 2; half++) {
                int row = rl + half * 8;
                if (row >= valid) continue;
                size_t rp = (size_t)(off + r0 + row) * DFF + c;
                #pragma unroll
                for (int u = 0; u < 2; u++) {
                    float v = d[half * 2 + u] + bias[c + u];
                    v = 0.5f * v * (1.0f + erff(v * 0.70710678118654752f));
                    g_hbuf[rp + u] = __float2half_rn(v);
                }
            }
        }
}

// ---------------- out += gate * (h @ w2[e] + b2[e])  (per-expert) ------------
__global__ void __launch_bounds__(256, 1) ffn2_gemm(
    int e, const float* __restrict__ B2, float* __restrict__ out)
{
    int cnt = g_cnt[e];
    int r0 = blockIdx.y * 128;
    if (r0 >= cnt) return;
    extern __shared__ char smem[];
    uint32_t sb = smem_u32(smem);
    ACC_INIT
    int off = g_off[e];
    int n0 = blockIdx.x * 256;
    int valid = cnt - r0; if (valid > 128) valid = 128;
    gemm256(sb, acc, g_hbuf, g_w2t + (size_t)e * DM * DFF,
            DFF, nullptr, off + r0, valid, n0);
    int lane = threadIdx.x & 31, wid = threadIdx.x >> 5;
    int wm = wid >> 2, wn = wid & 3;
    const float* bias = B2 + e * DM;
    #pragma unroll
    for (int mt = 0; mt < 4; mt++) {
        #pragma unroll
        for (int half = 0; half < 2; half++) {
            int row = wm * 64 + mt * 16 + (lane >> 2) + half * 8;
            if (row >= valid) continue;
            int slot = off + r0 + row;
            int tok = g_perm_tok[slot];
            float gate = g_slot_gate[slot];
            float* orow = out + (size_t)tok * DM;
            #pragma unroll
            for (int nt = 0; nt < 8; nt++) {
                int c = n0 + wn * 64 + nt * 8 + 2 * (lane & 3);
                float* d = acc[mt * 8 + nt];
                atomicAdd(orow + c,     gate * (d[half * 2]     + bias[c]));
                atomicAdd(orow + c + 1, gate * (d[half * 2 + 1] + bias[c + 1]));
            }
        }
    }
}

__global__ void scan_kernel(float* __restrict__ out, int out_size) {
    if (threadIdx.x == 0 && blockIdx.x == 0) {
        int o = 0;
        float aux = 0.f;
        for (int e = 0; e < NE; e++) { g_off[e] = o; o += g_cnt[e]; }
        for (int e = 0; e < NE; e++)
            aux += ((float)g_cnt[e] / (float)(NTOK * 2)) * (g_probsum[e] / (float)NTOK);
        if (out_size > NTOK * DM) out[NTOK * DM] = (float)NE * aux;
    }
}

__global__ void place_kernel() {
    int s = blockIdx.x * 256 + threadIdx.x;
    if (s >= NSLOT) return;
    int tok = s >> 1;
    int e = g_top_i[s];
    float w = g_top_w[s];
    int pos = atomicAdd(&g_cur[e], 1);
    int slot = g_off[e] + pos;
    g_perm_tok[slot] = tok;
    g_slot_gate[slot] = w;
}

// ===================== launch =====================
extern "C" void kernel_launch(void* const* d_in, const int* in_sizes, int n_in,
                              void* d_out, int out_size)
{
    const float* x        = (const float*)d_in[0];
    const float* ln1_g    = (const float*)d_in[2];
    const float* ln1_b    = (const float*)d_in[3];
    const float* w_qkv    = (const float*)d_in[4];
    const float* w_proj   = (const float*)d_in[5];
    const float* b_proj   = (const float*)d_in[6];
    const float* ln2_g    = (const float*)d_in[7];
    const float* ln2_b    = (const float*)d_in[8];
    const float* w_router = (const float*)d_in[9];
    const float* w1       = (const float*)d_in[10];
    const float* b1       = (const float*)d_in[11];
    const float* w2       = (const float*)d_in[12];
    const float* b2       = (const float*)d_in[13];
    float* out = (float*)d_out;

    static cudaStream_t s_side = nullptr, s_w = nullptr;
    static cudaEvent_t ev_fork = nullptr, ev_join = nullptr, ev_proj = nullptr;
    static cudaEvent_t ev_wqkv = nullptr, ev_ready = nullptr;
    static cudaEvent_t ev_d1 = nullptr, ev_d2 = nullptr;
    static bool attr_done = false;
    if (!attr_done) {
        cudaFuncSetAttribute(qkv_gemm,  cudaFuncAttributeMaxDynamicSharedMemorySize, GEMM_SMEM);
        cudaFuncSetAttribute(proj_gemm, cudaFuncAttributeMaxDynamicSharedMemorySize, GEMM_SMEM);
        cudaFuncSetAttribute(ffn1_gemm, cudaFuncAttributeMaxDynamicSharedMemorySize, GEMM_SMEM);
        cudaFuncSetAttribute(ffn2_gemm, cudaFuncAttributeMaxDynamicSharedMemorySize, GEMM_SMEM);
        cudaFuncSetAttribute(attn_kernel, cudaFuncAttributeMaxDynamicSharedMemorySize, ATTN_SMEM);
        cudaStreamCreateWithFlags(&s_side, cudaStreamNonBlocking);
        cudaStreamCreateWithFlags(&s_w, cudaStreamNonBlocking);
        cudaEventCreateWithFlags(&ev_fork, cudaEventDisableTiming);
        cudaEventCreateWithFlags(&ev_join, cudaEventDisableTiming);
        cudaEventCreateWithFlags(&ev_proj, cudaEventDisableTiming);
        cudaEventCreateWithFlags(&ev_wqkv, cudaEventDisableTiming);
        cudaEventCreateWithFlags(&ev_ready, cudaEventDisableTiming);
        cudaEventCreateWithFlags(&ev_d1, cudaEventDisableTiming);
        cudaEventCreateWithFlags(&ev_d2, cudaEventDisableTiming);
        attr_done = true;
    }

    h16 *p_qh, *p_kh, *p_vh;
    h16 *p_xn1_h, *p_attn_h, *p_xn2_h;
    h16 *p_wqkvt_h, *p_wprojt_h, *p_w1t, *p_w2t;
    cudaGetSymbolAddress((void**)&p_qh,   g_qh);
    cudaGetSymbolAddress((void**)&p_kh,   g_kh);
    cudaGetSymbolAddress((void**)&p_vh,   g_vh);
    cudaGetSymbolAddress((void**)&p_xn1_h, g_xn1_h);
    cudaGetSymbolAddress((void**)&p_attn_h, g_attn_h);
    cudaGetSymbolAddress((void**)&p_xn2_h, g_xn2_h);
    cudaGetSymbolAddress((void**)&p_wqkvt_h, g_wqkvt_h);
    cudaGetSymbolAddress((void**)&p_wprojt_h, g_wprojt_h);
    cudaGetSymbolAddress((void**)&p_w1t, g_w1t);
    cudaGetSymbolAddress((void**)&p_w2t, g_w2t);

    zero_small_kernel<<<1, 32>>>();
    cudaEventRecord(ev_fork, 0);

    // side stream A: w_qkv conv + rope table (overlap ln1)
    cudaStreamWaitEvent(s_w, ev_fork, 0);
    rope_tab_kernel<<<TT * 32 / 256, 256, 0, s_w>>>();
    trans_conv<<<dim3(3 * DM / 32, DM / 32, 1), 256, 0, s_w>>>(w_qkv, p_wqkvt_h, DM, 3 * DM);
    cudaEventRecord(ev_wqkv, s_w);

    // side stream B: w_proj + FFN weight conversion (overlap attention chain)
    cudaStreamWaitEvent(s_side, ev_fork, 0);
    trans_conv<<<dim3(DM / 32, DM / 32, 1), 256, 0, s_side>>>(w_proj, p_wprojt_h, DM, DM);
    cudaEventRecord(ev_proj, s_side);
    trans_conv<<<dim3(DFF / 32, DM / 32, NE), 256, 0, s_side>>>(w1, p_w1t, DM, DFF);
    trans_conv<<<dim3(DM / 32, DFF / 32, NE), 256, 0, s_side>>>(w2, p_w2t, DFF, DM);
    cudaEventRecord(ev_join, s_side);

    // main chain
    ln_kernel<<<NTOK, 256>>>(x, ln1_g, ln1_b, p_xn1_h);
    cudaStreamWaitEvent(0, ev_wqkv, 0);
    qkv_gemm<<<dim3(3 * DM / 256, NTOK / 128), 256, GEMM_SMEM>>>();   // + fused rope
    attn_kernel<<<NBH * (TT / 128), 256, ATTN_SMEM>>>(p_qh, p_kh, p_vh, p_attn_h);
    cudaStreamWaitEvent(0, ev_proj, 0);
    proj_gemm<<<dim3(DM / 256, NTOK / 128), 256, GEMM_SMEM>>>(b_proj, x, out);
    ln2_router_kernel<<<NTOK, 256>>>(out, ln2_g, ln2_b, p_xn2_h, w_router);
    scan_kernel<<<1, 1>>>(out, out_size);
    place_kernel<<<NSLOT / 256, 256>>>();
    cudaEventRecord(ev_ready, 0);

    // per-expert FFN pipeline across 3 existing streams:
    // ffn2(e) depends only on ffn1(e) (same-stream FIFO order).
    cudaStreamWaitEvent(0, ev_join, 0);          // main stream needs w1t/w2t
    cudaStreamWaitEvent(s_w, ev_ready, 0);       // expert streams need routing
    cudaStreamWaitEvent(s_w, ev_join, 0);
    cudaStreamWaitEvent(s_side, ev_ready, 0);    // (s_side already did w1/w2)
    cudaStream_t strs[3] = { (cudaStream_t)0, s_side, s_w };
    for (int e = 0; e < NE; e++) {
        cudaStream_t st = strs[e % 3];
        ffn1_gemm<<<dim3(DFF / 256, NSLOT / 128), 256, GEMM_SMEM, st>>>(e, b1);
        ffn2_gemm<<<dim3(DM / 256, NSLOT / 128), 256, GEMM_SMEM, st>>>(e, b2, out);
    }
    cudaEventRecord(ev_d1, s_side);
    cudaEventRecord(ev_d2, s_w);
    cudaStreamWaitEvent(0, ev_d1, 0);
    cudaStreamWaitEvent(0, ev_d2, 0);
}

// round 16
// speedup vs baseline: 1.0624x; 1.0624x over previous
#include <cuda_runtime.h>
#include <cuda_fp16.h>
#include <math.h>
#include <stdint.h>

#define NTOK 4096      // B*T
#define DM   1024
#define NH   16
#define HD   64
#define NE   8
#define DFF  4096
#define NSLOT 8192     // NTOK * TOP_K
#define TT   1024
#define NBH  64        // B * NH

typedef __half h16;

// ===================== scratch (static device memory) ========================
__device__ h16    g_xn1_h [NTOK * DM];
__device__ h16    g_qh    [NTOK * DM];   // [B,H,T,HD] fp16, pre-scaled 0.125
__device__ h16    g_kh    [NTOK * DM];
__device__ h16    g_vh    [NTOK * DM];
__device__ h16    g_attn_h[NTOK * DM];
__device__ h16    g_xn2_h [NTOK * DM];
__device__ h16    g_hbuf  [(size_t)NSLOT * DFF];
__device__ float2 g_rope_tab[TT * 32];

// transposed weights ([N,K] K-major per expert)
__device__ h16 g_wqkvt_h[3 * DM * DM];
__device__ h16 g_wprojt_h[DM * DM];
__device__ h16 g_w1t[(size_t)NE * DFF * DM];
__device__ h16 g_w2t[(size_t)NE * DM * DFF];

__device__ int   g_cnt[NE];
__device__ int   g_off[NE];
__device__ int   g_cur[NE];
__device__ float g_probsum[NE];
__device__ int   g_top_i[NSLOT];
__device__ float g_top_w[NSLOT];
__device__ int   g_perm_tok[NSLOT];
__device__ float g_slot_gate[NSLOT];

__device__ __forceinline__ uint32_t smem_u32(const void* p) {
    uint32_t a;
    asm("{ .reg .u64 t; cvta.to.shared.u64 t, %1; cvt.u32.u64 %0, t; }"
        : "=r"(a) : "l"(p));
    return a;
}
__device__ __forceinline__ void ldsm4(uint32_t* r, uint32_t addr) {
    asm volatile("ldmatrix.sync.aligned.m8n8.x4.shared.b16 {%0,%1,%2,%3}, [%4];"
                 : "=r"(r[0]), "=r"(r[1]), "=r"(r[2]), "=r"(r[3]) : "r"(addr));
}
__device__ __forceinline__ void ldsm4t(uint32_t* r, uint32_t addr) {
    asm volatile("ldmatrix.sync.aligned.m8n8.x4.trans.shared.b16 {%0,%1,%2,%3}, [%4];"
                 : "=r"(r[0]), "=r"(r[1]), "=r"(r[2]), "=r"(r[3]) : "r"(addr));
}
__device__ __forceinline__ void mma_f16(float* d, const uint32_t* a, const uint32_t* b) {
    asm volatile(
        "mma.sync.aligned.m16n8k16.row.col.f32.f16.f16.f32 "
        "{%0,%1,%2,%3}, {%4,%5,%6,%7}, {%8,%9}, {%0,%1,%2,%3};"
        : "+f"(d[0]), "+f"(d[1]), "+f"(d[2]), "+f"(d[3])
        : "r"(a[0]), "r"(a[1]), "r"(a[2]), "r"(a[3]), "r"(b[0]), "r"(b[1]));
}
__device__ __forceinline__ void cp_async16(uint32_t saddr, const void* g, uint32_t sz) {
    asm volatile("cp.async.cg.shared.global [%0], [%1], 16, %2;"
                 :: "r"(saddr), "l"(g), "r"(sz));
}
__device__ __forceinline__ void cp_commit() {
    asm volatile("cp.async.commit_group;");
}
template<int N> __device__ __forceinline__ void cp_wait() {
    asm volatile("cp.async.wait_group %0;" :: "n"(N));
}
__device__ __forceinline__ uint32_t sw128(uint32_t o) {
    return o ^ ((o >> 3) & 0x70u);
}
__device__ __forceinline__ uint32_t h2pack(float a, float b) {
    half2 h = __floats2half2_rn(a, b);
    return *(uint32_t*)&h;
}

// ===================== small helpers ====================
__global__ void zero_small_kernel() {
    int i = threadIdx.x;
    if (i < NE) { g_cnt[i] = 0; g_cur[i] = 0; g_probsum[i] = 0.f; }
}

// rope sincos table: tab[t*32+f] = (cos, sin)(t * 10000^(-f/32))
__global__ void __launch_bounds__(256) rope_tab_kernel() {
    int idx = blockIdx.x * 256 + threadIdx.x;
    int t = idx >> 5, f = idx & 31;
    float freq = exp2f(-(float)f * 0.41524101186092029f);
    float sv, cv;
    __sincosf((float)t * freq, &sv, &cv);
    g_rope_tab[idx] = make_float2(cv, sv);
}

// ---------------- transpose + convert: w[K,N] -> t[N,K] ----------------------
__global__ void __launch_bounds__(256) trans_conv(
    const float* __restrict__ w, h16* __restrict__ th, int K, int N)
{
    const size_t eoff = (size_t)blockIdx.z * K * N;
    const float* wp = w + eoff;
    h16* thp = th + eoff;
    __shared__ float t[32][33];
    int tx = threadIdx.x & 31, ty = threadIdx.x >> 5;
    int n0 = blockIdx.x * 32, k0 = blockIdx.y * 32;
    #pragma unroll
    for (int i = 0; i < 4; i++)
        t[ty + i * 8][tx] = wp[(size_t)(k0 + ty + i * 8) * N + n0 + tx];
    __syncthreads();
    #pragma unroll
    for (int i = 0; i < 4; i++) {
        float v = t[tx][ty + i * 8];
        int n = n0 + ty + i * 8, k = k0 + tx;
        thp[(size_t)n * K + k] = __float2half_rn(v);
    }
}

// ---------------- layernorm (256 thr/row) ----------------
__global__ void __launch_bounds__(256) ln_kernel(
    const float* __restrict__ x, const float* __restrict__ g,
    const float* __restrict__ b, h16* __restrict__ oh)
{
    int row = blockIdx.x;
    const float* xr = x + (size_t)row * DM;
    float v[4]; float s = 0.f, ss = 0.f;
    #pragma unroll
    for (int i = 0; i < 4; i++) {
        float u = xr[threadIdx.x + i * 256];
        v[i] = u; s += u; ss += u * u;
    }
    #pragma unroll
    for (int ofs = 16; ofs > 0; ofs >>= 1) {
        s  += __shfl_xor_sync(0xffffffffu, s,  ofs);
        ss += __shfl_xor_sync(0xffffffffu, ss, ofs);
    }
    __shared__ float sh[2][8];
    int warp = threadIdx.x >> 5, lane = threadIdx.x & 31;
    if (lane == 0) { sh[0][warp] = s; sh[1][warp] = ss; }
    __syncthreads();
    float S = 0.f, SS = 0.f;
    #pragma unroll
    for (int w = 0; w < 8; w++) { S += sh[0][w]; SS += sh[1][w]; }
    float mu  = S * (1.0f / DM);
    float var = SS * (1.0f / DM) - mu * mu;
    float inv = rsqrtf(var + 1e-5f);
    #pragma unroll
    for (int i = 0; i < 4; i++) {
        int idx = threadIdx.x + i * 256;
        float o = (v[i] - mu) * inv * g[idx] + b[idx];
        oh[(size_t)row * DM + idx] = __float2half_rn(o);
    }
}

// ---------------- fused ln2 + router (reads x2 from out) ---------------------
__global__ void __launch_bounds__(256) ln2_router_kernel(
    const float* __restrict__ x, const float* __restrict__ g,
    const float* __restrict__ b, h16* __restrict__ oh,
    const float* __restrict__ wr)
{
    int row = blockIdx.x, tid = threadIdx.x;
    const float* xr = x + (size_t)row * DM;
    float v[4]; float s = 0.f, ss = 0.f;
    #pragma unroll
    for (int i = 0; i < 4; i++) {
        float u = xr[tid + i * 256];
        v[i] = u; s += u; ss += u * u;
    }
    #pragma unroll
    for (int ofs = 16; ofs > 0; ofs >>= 1) {
        s  += __shfl_xor_sync(0xffffffffu, s,  ofs);
        ss += __shfl_xor_sync(0xffffffffu, ss, ofs);
    }
    __shared__ float sh[2][8];
    int warp = tid >> 5, lane = tid & 31;
    if (lane == 0) { sh[0][warp] = s; sh[1][warp] = ss; }
    __syncthreads();
    float S = 0.f, SS = 0.f;
    #pragma unroll
    for (int w = 0; w < 8; w++) { S += sh[0][w]; SS += sh[1][w]; }
    float mu  = S * (1.0f / DM);
    float var = SS * (1.0f / DM) - mu * mu;
    float inv = rsqrtf(var + 1e-5f);
    float pe[NE];
    #pragma unroll
    for (int e = 0; e < NE; e++) pe[e] = 0.f;
    #pragma unroll
    for (int i = 0; i < 4; i++) {
        int idx = tid + i * 256;
        float o = (v[i] - mu) * inv * g[idx] + b[idx];
        oh[(size_t)row * DM + idx] = __float2half_rn(o);
        const float* w = wr + idx * NE;
        #pragma unroll
        for (int e = 0; e < NE; e++) pe[e] += o * w[e];
    }
    __shared__ float red[NE][256];
    #pragma unroll
    for (int e = 0; e < NE; e++) red[e][tid] = pe[e];
    __syncthreads();
    for (int st = 128; st > 0; st >>= 1) {
        if (tid < st) {
            #pragma unroll
            for (int e = 0; e < NE; e++) red[e][tid] += red[e][tid + st];
        }
        __syncthreads();
    }
    if (tid == 0) {
        float lg[NE], mx = -1e30f;
        #pragma unroll
        for (int e = 0; e < NE; e++) { lg[e] = red[e][0]; mx = fmaxf(mx, lg[e]); }
        float se = 0.f, pr[NE];
        #pragma unroll
        for (int e = 0; e < NE; e++) { pr[e] = __expf(lg[e] - mx); se += pr[e]; }
        float invs = 1.0f / se;
        #pragma unroll
        for (int e = 0; e < NE; e++) {
            pr[e] *= invs;
            atomicAdd(&g_probsum[e], pr[e]);
        }
        int i0 = 0;
        #pragma unroll
        for (int e = 1; e < NE; e++) if (pr[e] > pr[i0]) i0 = e;
        int i1 = (i0 == 0) ? 1 : 0;
        #pragma unroll
        for (int e = 0; e < NE; e++) if (e != i0 && pr[e] > pr[i1]) i1 = e;
        float w0 = pr[i0], w1 = pr[i1], sw = 1.0f / (w0 + w1);
        g_top_i[row * 2] = i0; g_top_i[row * 2 + 1] = i1;
        g_top_w[row * 2] = w0 * sw; g_top_w[row * 2 + 1] = w1 * sw;
        atomicAdd(&g_cnt[i0], 1);
        atomicAdd(&g_cnt[i1], 1);
    }
}

// ---------------- tensor-core flash attention --------------------------------
#define ATTN_SMEM 49152
__global__ void __launch_bounds__(256, 2) attn_kernel(
    const h16* __restrict__ q, const h16* __restrict__ k,
    const h16* __restrict__ v, h16* __restrict__ oh)
{
    extern __shared__ char smem[];
    uint32_t sb = smem_u32(smem);
    const uint32_t SQ = 0, SKV = 16384, STG = 16384;

    int bh = blockIdx.x & (NBH - 1);
    int chunk = (TT / 128 - 1) - (blockIdx.x >> 6);
    int qb0 = chunk * 128;
    int tid = threadIdx.x, lane = tid & 31, w = tid >> 5;
    const h16* qb = q + (size_t)bh * TT * HD;
    const h16* kb = k + (size_t)bh * TT * HD;
    const h16* vb = v + (size_t)bh * TT * HD;

    for (int i = tid; i < 128 * 8; i += 256) {
        int r = i >> 3, ch = i & 7;
        uint32_t so = sw128((uint32_t)(r * 128 + ch * 16));
        *(uint4*)(smem + SQ + so) = *(const uint4*)(qb + (size_t)(qb0 + r) * HD + ch * 8);
    }

    auto load_kv = [&](int j0, int st) {
        uint32_t s0 = sb + SKV + (uint32_t)st * STG;
        #pragma unroll
        for (int i = 0; i < 2; i++) {
            int idx = tid + i * 256;
            int r = idx >> 3, ch = idx & 7;
            uint32_t so = sw128((uint32_t)(r * 128 + ch * 16));
            cp_async16(s0 + so, kb + (size_t)(j0 + r) * HD + ch * 8, 16);
            cp_async16(s0 + 8192 + so, vb + (size_t)(j0 + r) * HD + ch * 8, 16);
        }
        cp_commit();
    };
    load_kv(0, 0);
    __syncthreads();

    uint32_t qf[4][4];
    #pragma unroll
    for (int ks = 0; ks < 4; ks++) {
        int row = w * 16 + (lane & 15);
        uint32_t so = sw128((uint32_t)(row * 128 + ks * 32 + (lane >> 4) * 16));
        ldsm4(qf[ks], sb + SQ + so);
    }

    float oacc[8][4];
    #pragma unroll
    for (int i = 0; i < 8; i++)
        #pragma unroll
        for (int j = 0; j < 4; j++) oacc[i][j] = 0.f;
    float mrun[2] = {-1e30f, -1e30f}, lsum[2] = {0.f, 0.f};

    const int wrow = qb0 + w * 16 + (lane >> 2);
    const int wt_last = qb0 + w * 16 + 15;
    const int wt_first = qb0 + w * 16;
    const int ntiles = (qb0 + 128) / 64;

    for (int ti = 0; ti < ntiles; ti++) {
        int j0 = ti * 64;
        if (ti + 1 < ntiles) { load_kv(j0 + 64, (ti + 1) & 1); cp_wait<1>(); }
        else cp_wait<0>();
        __syncthreads();
        if (j0 <= wt_last) {
            uint32_t s0 = sb + SKV + (uint32_t)(ti & 1) * STG;
            float sacc[8][4];
            #pragma unroll
            for (int i = 0; i < 8; i++)
                #pragma unroll
                for (int j = 0; j < 4; j++) sacc[i][j] = 0.f;
            #pragma unroll
            for (int ks = 0; ks < 4; ks++) {
                #pragma unroll
                for (int n2 = 0; n2 < 4; n2++) {
                    int row = n2 * 16 + (lane & 15);
                    uint32_t so = sw128((uint32_t)(row * 128 + ks * 32 + (lane >> 4) * 16));
                    uint32_t t4[4]; ldsm4(t4, s0 + so);
                    uint32_t b0[2] = {t4[0], t4[2]}, b1[2] = {t4[1], t4[3]};
                    mma_f16(sacc[2 * n2], qf[ks], b0);
                    mma_f16(sacc[2 * n2 + 1], qf[ks], b1);
                }
            }
            if (j0 + 63 > wt_first) {
                #pragma unroll
                for (int nt = 0; nt < 8; nt++)
                    #pragma unroll
                    for (int r = 0; r < 4; r++) {
                        int col = j0 + 8 * nt + 2 * (lane & 3) + (r & 1);
                        int rowt = wrow + 8 * (r >> 1);
                        if (col > rowt) sacc[nt][r] = -1e30f;
                    }
            }
            float psc[2];
            #pragma unroll
            for (int hh = 0; hh < 2; hh++) {
                float mx = -1e30f;
                #pragma unroll
                for (int nt = 0; nt < 8; nt++) {
                    mx = fmaxf(mx, sacc[nt][2 * hh]);
                    mx = fmaxf(mx, sacc[nt][2 * hh + 1]);
                }
                mx = fmaxf(mx, __shfl_xor_sync(0xffffffffu, mx, 1));
                mx = fmaxf(mx, __shfl_xor_sync(0xffffffffu, mx, 2));
                float nm = fmaxf(mrun[hh], mx);
                float sc = __expf(mrun[hh] - nm);
                mrun[hh] = nm;
                float sum = 0.f;
                #pragma unroll
                for (int nt = 0; nt < 8; nt++) {
                    float p0 = __expf(sacc[nt][2 * hh] - nm);
                    float p1 = __expf(sacc[nt][2 * hh + 1] - nm);
                    sacc[nt][2 * hh] = p0; sacc[nt][2 * hh + 1] = p1;
                    sum += p0 + p1;
                }
                sum += __shfl_xor_sync(0xffffffffu, sum, 1);
                sum += __shfl_xor_sync(0xffffffffu, sum, 2);
                lsum[hh] = lsum[hh] * sc + sum;
                psc[hh] = sc;
            }
            #pragma unroll
            for (int nt = 0; nt < 8; nt++)
                #pragma unroll
                for (int r = 0; r < 4; r++)
                    oacc[nt][r] *= psc[r >> 1];
            uint32_t pf[4][4];
            #pragma unroll
            for (int kt = 0; kt < 4; kt++) {
                pf[kt][0] = h2pack(sacc[2 * kt][0], sacc[2 * kt][1]);
                pf[kt][1] = h2pack(sacc[2 * kt][2], sacc[2 * kt][3]);
                pf[kt][2] = h2pack(sacc[2 * kt + 1][0], sacc[2 * kt + 1][1]);
                pf[kt][3] = h2pack(sacc[2 * kt + 1][2], sacc[2 * kt + 1][3]);
            }
            uint32_t sv = s0 + 8192;
            int g = lane >> 3, rr = lane & 7;
            #pragma unroll
            for (int dp = 0; dp < 4; dp++) {
                #pragma unroll
                for (int kt = 0; kt < 4; kt++) {
                    int kvr = 16 * kt + 8 * (g & 1) + rr;
                    int dc = dp * 16 + 8 * (g >> 1);
                    uint32_t so = sw128((uint32_t)(kvr * 128 + dc * 2));
                    uint32_t t4[4]; ldsm4t(t4, sv + so);
                    uint32_t b0[2] = {t4[0], t4[1]}, b1[2] = {t4[2], t4[3]};
                    mma_f16(oacc[2 * dp], pf[kt], b0);
                    mma_f16(oacc[2 * dp + 1], pf[kt], b1);
                }
            }
        }
        __syncthreads();
    }
    int b = bh >> 4, hH = bh & 15;
    #pragma unroll
    for (int hh = 0; hh < 2; hh++) {
        float inv = 1.0f / lsum[hh];
        int t = wrow + 8 * hh;
        size_t op = ((size_t)(b * TT + t)) * DM + hH * HD;
        #pragma unroll
        for (int nt = 0; nt < 8; nt++) {
            int d = 8 * nt + 2 * (lane & 3);
            half2 hv = __floats2half2_rn(oacc[nt][2 * hh] * inv, oacc[nt][2 * hh + 1] * inv);
            *(half2*)(oh + op + d) = hv;
        }
    }
}

// ===================== 128x256 HMMA GEMM core (4-stage, occ 1) ===============
// K range [kstart, kstart+kcount) of rows with stride Kstride.
#define NSTG 4
__device__ __forceinline__ void gemm256(
    uint32_t sb, float (*acc)[4],
    const h16* __restrict__ A, const h16* __restrict__ B,
    int Kstride, int kstart, int kcount,
    const int* __restrict__ perm, int row_base, int valid, int n0)
{
    constexpr uint32_t T_B = 16384;
    constexpr uint32_t STAGE = 49152;
    const int tid = threadIdx.x, lane = tid & 31, wid = tid >> 5;
    const int wm = wid >> 2, wn = wid & 3;
    const int nkb = kcount >> 6;

    const int arow = tid >> 3, ach = tid & 7;
    uint32_t asz[4];
    size_t aoff[4];
    #pragma unroll
    for (int it = 0; it < 4; it++) {
        int row = arow + it * 32;
        asz[it] = (row < valid) ? 16u : 0u;
        int gra = (row < valid) ? (perm ? perm[row_base + row] : (row_base + row)) : 0;
        aoff[it] = (size_t)gra * Kstride;
    }

    auto load_stage = [&](int kb) {
        uint32_t s0 = sb + (uint32_t)(kb & (NSTG - 1)) * STAGE;
        int koff = kstart + kb * 64 + ach * 8;
        #pragma unroll
        for (int it = 0; it < 4; it++) {
            int row = arow + it * 32;
            uint32_t so = sw128((uint32_t)(row * 128 + ach * 16));
            cp_async16(s0 + so, A + aoff[it] + koff, asz[it]);
        }
        #pragma unroll
        for (int it = 0; it < 8; it++) {
            int row = arow + it * 32;
            uint32_t so = sw128((uint32_t)(row * 128 + ach * 16));
            cp_async16(s0 + T_B + so, B + (size_t)(n0 + row) * Kstride + koff, 16u);
        }
        cp_commit();
    };

    #pragma unroll
    for (int s = 0; s < NSTG - 1; s++)
        if (s < nkb) load_stage(s);

    for (int kb = 0; kb < nkb; kb++) {
        if (kb + NSTG - 1 < nkb) { load_stage(kb + NSTG - 1); cp_wait<NSTG - 1>(); }
        else {
            int rem = nkb - 1 - kb;
            if (rem >= 2) cp_wait<2>();
            else if (rem == 1) cp_wait<1>();
            else cp_wait<0>();
        }
        __syncthreads();
        uint32_t s0 = sb + (uint32_t)(kb & (NSTG - 1)) * STAGE;
        #pragma unroll
        for (int ks = 0; ks < 4; ks++) {
            uint32_t af[4][4];
            #pragma unroll
            for (int mt = 0; mt < 4; mt++) {
                int row = wm * 64 + mt * 16 + (lane & 15);
                uint32_t so = sw128((uint32_t)(row * 128 + ks * 32 + (lane >> 4) * 16));
                ldsm4(af[mt], s0 + so);
            }
            uint32_t bf[8][2];
            #pragma unroll
            for (int n2 = 0; n2 < 4; n2++) {
                int row = wn * 64 + n2 * 16 + (lane & 15);
                uint32_t so = sw128((uint32_t)(row * 128 + ks * 32 + (lane >> 4) * 16));
                uint32_t t4[4];
                ldsm4(t4, s0 + T_B + so);
                bf[n2 * 2][0] = t4[0]; bf[n2 * 2][1] = t4[2];
                bf[n2 * 2 + 1][0] = t4[1]; bf[n2 * 2 + 1][1] = t4[3];
            }
            #pragma unroll
            for (int mt = 0; mt < 4; mt++)
                #pragma unroll
                for (int nt = 0; nt < 8; nt++)
                    mma_f16(acc[mt * 8 + nt], af[mt], bf[nt]);
        }
        __syncthreads();
    }
}
// acc[mt*8+nt][r]: row = wm*64 + mt*16 + lane/4 + 8*(r>>1)
//                  col = wn*64 + nt*8  + 2*(lane&3) + (r&1)

#define GEMM_SMEM 196608
#define ACC_INIT float acc[32][4]; \
    _Pragma("unroll") for (int i = 0; i < 32; i++) \
    _Pragma("unroll") for (int j = 0; j < 4; j++) acc[i][j] = 0.f;

// ---------------- qkv gemm + fused rope -> fp16 q/k/v ------------------------
__global__ void __launch_bounds__(256, 1) qkv_gemm() {
    extern __shared__ char smem[];
    uint32_t sb = smem_u32(smem);
    ACC_INIT
    int m0 = blockIdx.y * 128, n0 = blockIdx.x * 256;
    gemm256(sb, acc, g_xn1_h, g_wqkvt_h, DM, 0, DM, nullptr, m0, 128, n0);
    int lane = threadIdx.x & 31, wid = threadIdx.x >> 5;
    int wm = wid >> 2, wn = wid & 3;
    int c_base = n0 + wn * 64;
    int sec = c_base >> 10;             // 0=q, 1=k, 2=v
    int h = (c_base & 1023) >> 6;       // head index
    h16* dstq = (sec == 0) ? g_qh : g_kh;
    #pragma unroll
    for (int mt = 0; mt < 4; mt++) {
        #pragma unroll
        for (int half = 0; half < 2; half++) {
            int rg = m0 + wm * 64 + mt * 16 + (lane >> 2) + half * 8;
            int t = rg & (TT - 1), bb = rg >> 10;
            size_t dbase = ((size_t)((bb * NH + h) * TT) + t) * HD;
            #pragma unroll
            for (int nt = 0; nt < 4; nt++) {
                int d = nt * 8 + 2 * (lane & 3);
                float a0 = acc[mt * 8 + nt][half * 2];
                float a1 = acc[mt * 8 + nt][half * 2 + 1];
                float b0 = acc[mt * 8 + nt + 4][half * 2];
                float b1 = acc[mt * 8 + nt + 4][half * 2 + 1];
                if (sec == 2) {
                    *(half2*)(g_vh + dbase + d)      = __floats2half2_rn(a0, a1);
                    *(half2*)(g_vh + dbase + d + 32) = __floats2half2_rn(b0, b1);
                } else {
                    float2 cs0 = g_rope_tab[t * 32 + d];
                    float2 cs1 = g_rope_tab[t * 32 + d + 1];
                    float lo0 = a0 * cs0.x - b0 * cs0.y;
                    float lo1 = a1 * cs1.x - b1 * cs1.y;
                    float hi0 = b0 * cs0.x + a0 * cs0.y;
                    float hi1 = b1 * cs1.x + a1 * cs1.y;
                    if (sec == 0) { lo0 *= 0.125f; lo1 *= 0.125f; hi0 *= 0.125f; hi1 *= 0.125f; }
                    *(half2*)(dstq + dbase + d)      = __floats2half2_rn(lo0, lo1);
                    *(half2*)(dstq + dbase + d + 32) = __floats2half2_rn(hi0, hi1);
                }
            }
        }
    }
}

// ---------------- x2 = attn @ w_proj + b_proj + x -> out ---------------------
__global__ void __launch_bounds__(256, 1) proj_gemm(
    const float* __restrict__ bias, const float* __restrict__ resid,
    float* __restrict__ out)
{
    extern __shared__ char smem[];
    uint32_t sb = smem_u32(smem);
    ACC_INIT
    int m0 = blockIdx.y * 128, n0 = blockIdx.x * 256;
    gemm256(sb, acc, g_attn_h, g_wprojt_h, DM, 0, DM, nullptr, m0, 128, n0);
    int lane = threadIdx.x & 31, wid = threadIdx.x >> 5;
    int wm = wid >> 2, wn = wid & 3;
    #pragma unroll
    for (int mt = 0; mt < 4; mt++)
        #pragma unroll
        for (int nt = 0; nt < 8; nt++) {
            int r = m0 + wm * 64 + mt * 16 + (lane >> 2);
            int c = n0 + wn * 64 + nt * 8 + 2 * (lane & 3);
            float* d = acc[mt * 8 + nt];
            size_t p0 = (size_t)r * DM + c;
            size_t p1 = (size_t)(r + 8) * DM + c;
            out[p0]     = d[0] + bias[c]     + resid[p0];
            out[p0 + 1] = d[1] + bias[c + 1] + resid[p0 + 1];
            out[p1]     = d[2] + bias[c]     + resid[p1];
            out[p1 + 1] = d[3] + bias[c + 1] + resid[p1 + 1];
        }
}

// ---------------- h = gelu(gather(xn2) @ w1[e] + b1[e]) ----------------------
__global__ void __launch_bounds__(256, 1) ffn1_gemm(const float* __restrict__ B1) {
    int e = blockIdx.z;
    int cnt = g_cnt[e];
    int r0 = blockIdx.y * 128;
    if (r0 >= cnt) return;
    extern __shared__ char smem[];
    uint32_t sb = smem_u32(smem);
    ACC_INIT
    int off = g_off[e];
    int n0 = blockIdx.x * 256;
    int valid = cnt - r0; if (valid > 128) valid = 128;
    gemm256(sb, acc, g_xn2_h, g_w1t + (size_t)e * DFF * DM,
            DM, 0, DM, g_perm_tok, off + r0, valid, n0);
    int lane = threadIdx.x & 31, wid = threadIdx.x >> 5;
    int wm = wid >> 2, wn = wid & 3;
    const float* bias = B1 + e * DFF;
    #pragma unroll
    for (int mt = 0; mt < 4; mt++)
        #pragma unroll
        for (int nt = 0; nt < 8; nt++) {
            int rl = wm * 64 + mt * 16 + (lane >> 2);
            int c = n0 + wn * 64 + nt * 8 + 2 * (lane & 3);
            float* d = acc[mt * 8 + nt];
            #pragma unroll
            for (int half = 0; half < 2; half++) {
                int row = rl + half * 8;
                if (row >= valid) continue;
                size_t rp = (size_t)(off + r0 + row) * DFF + c;
                #pragma unroll
                for (int u = 0; u < 2; u++) {
                    float v = d[half * 2 + u] + bias[c + u];
                    v = 0.5f * v * (1.0f + erff(v * 0.70710678118654752f));
                    g_hbuf[rp + u] = __float2half_rn(v);
                }
            }
        }
}

// ---------------- out += gate * (h @ w2[e] + b2[e])  (K-split 4) -------------
#define KSPL 4
__global__ void __launch_bounds__(256, 1) ffn2_gemm(
    const float* __restrict__ B2, float* __restrict__ out)
{
    int e  = blockIdx.z >> 2;
    int kc = blockIdx.z & 3;
    int cnt = g_cnt[e];
    int r0 = blockIdx.y * 128;
    if (r0 >= cnt) return;
    extern __shared__ char smem[];
    uint32_t sb = smem_u32(smem);
    ACC_INIT
    int off = g_off[e];
    int n0 = blockIdx.x * 256;
    int valid = cnt - r0; if (valid > 128) valid = 128;
    gemm256(sb, acc, g_hbuf, g_w2t + (size_t)e * DM * DFF,
            DFF, kc * (DFF / KSPL), DFF / KSPL, nullptr, off + r0, valid, n0);
    int lane = threadIdx.x & 31, wid = threadIdx.x >> 5;
    int wm = wid >> 2, wn = wid & 3;
    const float* bias = B2 + e * DM;
    const bool add_bias = (kc == 0);
    #pragma unroll
    for (int mt = 0; mt < 4; mt++) {
        #pragma unroll
        for (int half = 0; half < 2; half++) {
            int row = wm * 64 + mt * 16 + (lane >> 2) + half * 8;
            if (row >= valid) continue;
            int slot = off + r0 + row;
            int tok = g_perm_tok[slot];
            float gate = g_slot_gate[slot];
            float* orow = out + (size_t)tok * DM;
            #pragma unroll
            for (int nt = 0; nt < 8; nt++) {
                int c = n0 + wn * 64 + nt * 8 + 2 * (lane & 3);
                float* d = acc[mt * 8 + nt];
                float b0 = add_bias ? bias[c] : 0.f;
                float b1 = add_bias ? bias[c + 1] : 0.f;
                atomicAdd(orow + c,     gate * (d[half * 2]     + b0));
                atomicAdd(orow + c + 1, gate * (d[half * 2 + 1] + b1));
            }
        }
    }
}

__global__ void scan_kernel(float* __restrict__ out, int out_size) {
    if (threadIdx.x == 0 && blockIdx.x == 0) {
        int o = 0;
        float aux = 0.f;
        for (int e = 0; e < NE; e++) { g_off[e] = o; o += g_cnt[e]; }
        for (int e = 0; e < NE; e++)
            aux += ((float)g_cnt[e] / (float)(NTOK * 2)) * (g_probsum[e] / (float)NTOK);
        if (out_size > NTOK * DM) out[NTOK * DM] = (float)NE * aux;
    }
}

__global__ void place_kernel() {
    int s = blockIdx.x * 256 + threadIdx.x;
    if (s >= NSLOT) return;
    int tok = s >> 1;
    int e = g_top_i[s];
    float w = g_top_w[s];
    int pos = atomicAdd(&g_cur[e], 1);
    int slot = g_off[e] + pos;
    g_perm_tok[slot] = tok;
    g_slot_gate[slot] = w;
}

// ===================== launch =====================
extern "C" void kernel_launch(void* const* d_in, const int* in_sizes, int n_in,
                              void* d_out, int out_size)
{
    const float* x        = (const float*)d_in[0];
    const float* ln1_g    = (const float*)d_in[2];
    const float* ln1_b    = (const float*)d_in[3];
    const float* w_qkv    = (const float*)d_in[4];
    const float* w_proj   = (const float*)d_in[5];
    const float* b_proj   = (const float*)d_in[6];
    const float* ln2_g    = (const float*)d_in[7];
    const float* ln2_b    = (const float*)d_in[8];
    const float* w_router = (const float*)d_in[9];
    const float* w1       = (const float*)d_in[10];
    const float* b1       = (const float*)d_in[11];
    const float* w2       = (const float*)d_in[12];
    const float* b2       = (const float*)d_in[13];
    float* out = (float*)d_out;

    static cudaStream_t s_side = nullptr;
    static cudaEvent_t ev_fork = nullptr, ev_join = nullptr, ev_proj = nullptr;
    static bool attr_done = false;
    if (!attr_done) {
        cudaFuncSetAttribute(qkv_gemm,  cudaFuncAttributeMaxDynamicSharedMemorySize, GEMM_SMEM);
        cudaFuncSetAttribute(proj_gemm, cudaFuncAttributeMaxDynamicSharedMemorySize, GEMM_SMEM);
        cudaFuncSetAttribute(ffn1_gemm, cudaFuncAttributeMaxDynamicSharedMemorySize, GEMM_SMEM);
        cudaFuncSetAttribute(ffn2_gemm, cudaFuncAttributeMaxDynamicSharedMemorySize, GEMM_SMEM);
        cudaFuncSetAttribute(attn_kernel, cudaFuncAttributeMaxDynamicSharedMemorySize, ATTN_SMEM);
        cudaStreamCreateWithFlags(&s_side, cudaStreamNonBlocking);
        cudaEventCreateWithFlags(&ev_fork, cudaEventDisableTiming);
        cudaEventCreateWithFlags(&ev_join, cudaEventDisableTiming);
        cudaEventCreateWithFlags(&ev_proj, cudaEventDisableTiming);
        attr_done = true;
    }

    h16 *p_qh, *p_kh, *p_vh;
    h16 *p_xn1_h, *p_attn_h, *p_xn2_h;
    h16 *p_wqkvt_h, *p_wprojt_h, *p_w1t, *p_w2t;
    cudaGetSymbolAddress((void**)&p_qh,   g_qh);
    cudaGetSymbolAddress((void**)&p_kh,   g_kh);
    cudaGetSymbolAddress((void**)&p_vh,   g_vh);
    cudaGetSymbolAddress((void**)&p_xn1_h, g_xn1_h);
    cudaGetSymbolAddress((void**)&p_attn_h, g_attn_h);
    cudaGetSymbolAddress((void**)&p_xn2_h, g_xn2_h);
    cudaGetSymbolAddress((void**)&p_wqkvt_h, g_wqkvt_h);
    cudaGetSymbolAddress((void**)&p_wprojt_h, g_wprojt_h);
    cudaGetSymbolAddress((void**)&p_w1t, g_w1t);
    cudaGetSymbolAddress((void**)&p_w2t, g_w2t);

    zero_small_kernel<<<1, 32>>>();
    rope_tab_kernel<<<TT * 32 / 256, 256>>>();

    // fork: w_proj + FFN weight conversion on side stream (overlap attention chain)
    cudaEventRecord(ev_fork, 0);
    cudaStreamWaitEvent(s_side, ev_fork, 0);
    trans_conv<<<dim3(DM / 32, DM / 32, 1), 256, 0, s_side>>>(w_proj, p_wprojt_h, DM, DM);
    cudaEventRecord(ev_proj, s_side);
    trans_conv<<<dim3(DFF / 32, DM / 32, NE), 256, 0, s_side>>>(w1, p_w1t, DM, DFF);
    trans_conv<<<dim3(DM / 32, DFF / 32, NE), 256, 0, s_side>>>(w2, p_w2t, DFF, DM);
    cudaEventRecord(ev_join, s_side);

    // main chain
    trans_conv<<<dim3(3 * DM / 32, DM / 32, 1), 256>>>(w_qkv, p_wqkvt_h, DM, 3 * DM);
    ln_kernel<<<NTOK, 256>>>(x, ln1_g, ln1_b, p_xn1_h);
    qkv_gemm<<<dim3(3 * DM / 256, NTOK / 128), 256, GEMM_SMEM>>>();   // + fused rope
    attn_kernel<<<NBH * (TT / 128), 256, ATTN_SMEM>>>(p_qh, p_kh, p_vh, p_attn_h);
    cudaStreamWaitEvent(0, ev_proj, 0);
    proj_gemm<<<dim3(DM / 256, NTOK / 128), 256, GEMM_SMEM>>>(b_proj, x, out);
    ln2_router_kernel<<<NTOK, 256>>>(out, ln2_g, ln2_b, p_xn2_h, w_router);
    scan_kernel<<<1, 1>>>(out, out_size);
    place_kernel<<<NSLOT / 256, 256>>>();

    // join before expert GEMMs. y-grid = NTOK/128 (max tokens per expert).
    cudaStreamWaitEvent(0, ev_join, 0);
    ffn1_gemm<<<dim3(DFF / 256, NTOK / 128, NE), 256, GEMM_SMEM>>>(b1);
    ffn2_gemm<<<dim3(DM / 256, NTOK / 128, NE * KSPL), 256, GEMM_SMEM>>>(b2, out);
}

// round 17
// speedup vs baseline: 1.1008x; 1.0362x over previous
#include <cuda_runtime.h>
#include <cuda_fp16.h>
#include <math.h>
#include <stdint.h>

#define NTOK 4096      // B*T
#define DM   1024
#define NH   16
#define HD   64
#define NE   8
#define DFF  4096
#define NSLOT 8192     // NTOK * TOP_K
#define TT   1024
#define NBH  64        // B * NH

typedef __half h16;

// ===================== scratch (static device memory) ========================
__device__ h16    g_xn1_h [NTOK * DM];
__device__ h16    g_qh    [NTOK * DM];   // [B,H,T,HD] fp16, pre-scaled 0.125
__device__ h16    g_kh    [NTOK * DM];
__device__ h16    g_vh    [NTOK * DM];
__device__ h16    g_attn_h[NTOK * DM];
__device__ h16    g_xn2_h [NTOK * DM];
__device__ h16    g_hbuf  [(size_t)NSLOT * DFF];
__device__ float2 g_rope_tab[TT * 32];

// transposed weights ([N,K] K-major per expert)
__device__ h16 g_wqkvt_h[3 * DM * DM];
__device__ h16 g_wprojt_h[DM * DM];
__device__ h16 g_w1t[(size_t)NE * DFF * DM];
__device__ h16 g_w2t[(size_t)NE * DM * DFF];

__device__ int   g_cnt[NE];
__device__ int   g_off[NE];
__device__ int   g_cur[NE];
__device__ float g_probsum[NE];
__device__ int   g_top_i[NSLOT];
__device__ float g_top_w[NSLOT];
__device__ int   g_perm_tok[NSLOT];
__device__ float g_slot_gate[NSLOT];

__device__ __forceinline__ uint32_t smem_u32(const void* p) {
    uint32_t a;
    asm("{ .reg .u64 t; cvta.to.shared.u64 t, %1; cvt.u32.u64 %0, t; }"
        : "=r"(a) : "l"(p));
    return a;
}
__device__ __forceinline__ void ldsm4(uint32_t* r, uint32_t addr) {
    asm volatile("ldmatrix.sync.aligned.m8n8.x4.shared.b16 {%0,%1,%2,%3}, [%4];"
                 : "=r"(r[0]), "=r"(r[1]), "=r"(r[2]), "=r"(r[3]) : "r"(addr));
}
__device__ __forceinline__ void ldsm4t(uint32_t* r, uint32_t addr) {
    asm volatile("ldmatrix.sync.aligned.m8n8.x4.trans.shared.b16 {%0,%1,%2,%3}, [%4];"
                 : "=r"(r[0]), "=r"(r[1]), "=r"(r[2]), "=r"(r[3]) : "r"(addr));
}
__device__ __forceinline__ void mma_f16(float* d, const uint32_t* a, const uint32_t* b) {
    asm volatile(
        "mma.sync.aligned.m16n8k16.row.col.f32.f16.f16.f32 "
        "{%0,%1,%2,%3}, {%4,%5,%6,%7}, {%8,%9}, {%0,%1,%2,%3};"
        : "+f"(d[0]), "+f"(d[1]), "+f"(d[2]), "+f"(d[3])
        : "r"(a[0]), "r"(a[1]), "r"(a[2]), "r"(a[3]), "r"(b[0]), "r"(b[1]));
}
__device__ __forceinline__ void cp_async16(uint32_t saddr, const void* g, uint32_t sz) {
    asm volatile("cp.async.cg.shared.global [%0], [%1], 16, %2;"
                 :: "r"(saddr), "l"(g), "r"(sz));
}
__device__ __forceinline__ void cp_commit() {
    asm volatile("cp.async.commit_group;");
}
template<int N> __device__ __forceinline__ void cp_wait() {
    asm volatile("cp.async.wait_group %0;" :: "n"(N));
}
__device__ __forceinline__ uint32_t sw128(uint32_t o) {
    return o ^ ((o >> 3) & 0x70u);
}
__device__ __forceinline__ uint32_t h2pack(float a, float b) {
    half2 h = __floats2half2_rn(a, b);
    return *(uint32_t*)&h;
}

// ===================== small helpers ====================
__global__ void zero_small_kernel() {
    int i = threadIdx.x;
    if (i < NE) { g_cnt[i] = 0; g_cur[i] = 0; g_probsum[i] = 0.f; }
}

// rope sincos table: tab[t*32+f] = (cos, sin)(t * 10000^(-f/32))
__global__ void __launch_bounds__(256) rope_tab_kernel() {
    int idx = blockIdx.x * 256 + threadIdx.x;
    int t = idx >> 5, f = idx & 31;
    float freq = exp2f(-(float)f * 0.41524101186092029f);
    float sv, cv;
    __sincosf((float)t * freq, &sv, &cv);
    g_rope_tab[idx] = make_float2(cv, sv);
}

// ---------------- transpose + convert: w[K,N] -> t[N,K] ----------------------
__global__ void __launch_bounds__(256) trans_conv(
    const float* __restrict__ w, h16* __restrict__ th, int K, int N)
{
    const size_t eoff = (size_t)blockIdx.z * K * N;
    const float* wp = w + eoff;
    h16* thp = th + eoff;
    __shared__ float t[32][33];
    int tx = threadIdx.x & 31, ty = threadIdx.x >> 5;
    int n0 = blockIdx.x * 32, k0 = blockIdx.y * 32;
    #pragma unroll
    for (int i = 0; i < 4; i++)
        t[ty + i * 8][tx] = wp[(size_t)(k0 + ty + i * 8) * N + n0 + tx];
    __syncthreads();
    #pragma unroll
    for (int i = 0; i < 4; i++) {
        float v = t[tx][ty + i * 8];
        int n = n0 + ty + i * 8, k = k0 + tx;
        thp[(size_t)n * K + k] = __float2half_rn(v);
    }
}

// ---------------- layernorm (256 thr/row) ----------------
__global__ void __launch_bounds__(256) ln_kernel(
    const float* __restrict__ x, const float* __restrict__ g,
    const float* __restrict__ b, h16* __restrict__ oh)
{
    int row = blockIdx.x;
    const float* xr = x + (size_t)row * DM;
    float v[4]; float s = 0.f, ss = 0.f;
    #pragma unroll
    for (int i = 0; i < 4; i++) {
        float u = xr[threadIdx.x + i * 256];
        v[i] = u; s += u; ss += u * u;
    }
    #pragma unroll
    for (int ofs = 16; ofs > 0; ofs >>= 1) {
        s  += __shfl_xor_sync(0xffffffffu, s,  ofs);
        ss += __shfl_xor_sync(0xffffffffu, ss, ofs);
    }
    __shared__ float sh[2][8];
    int warp = threadIdx.x >> 5, lane = threadIdx.x & 31;
    if (lane == 0) { sh[0][warp] = s; sh[1][warp] = ss; }
    __syncthreads();
    float S = 0.f, SS = 0.f;
    #pragma unroll
    for (int w = 0; w < 8; w++) { S += sh[0][w]; SS += sh[1][w]; }
    float mu  = S * (1.0f / DM);
    float var = SS * (1.0f / DM) - mu * mu;
    float inv = rsqrtf(var + 1e-5f);
    #pragma unroll
    for (int i = 0; i < 4; i++) {
        int idx = threadIdx.x + i * 256;
        float o = (v[i] - mu) * inv * g[idx] + b[idx];
        oh[(size_t)row * DM + idx] = __float2half_rn(o);
    }
}

// ---------------- fused ln2 + router (reads x2 from out) ---------------------
__global__ void __launch_bounds__(256) ln2_router_kernel(
    const float* __restrict__ x, const float* __restrict__ g,
    const float* __restrict__ b, h16* __restrict__ oh,
    const float* __restrict__ wr)
{
    int row = blockIdx.x, tid = threadIdx.x;
    const float* xr = x + (size_t)row * DM;
    float v[4]; float s = 0.f, ss = 0.f;
    #pragma unroll
    for (int i = 0; i < 4; i++) {
        float u = xr[tid + i * 256];
        v[i] = u; s += u; ss += u * u;
    }
    #pragma unroll
    for (int ofs = 16; ofs > 0; ofs >>= 1) {
        s  += __shfl_xor_sync(0xffffffffu, s,  ofs);
        ss += __shfl_xor_sync(0xffffffffu, ss, ofs);
    }
    __shared__ float sh[2][8];
    int warp = tid >> 5, lane = tid & 31;
    if (lane == 0) { sh[0][warp] = s; sh[1][warp] = ss; }
    __syncthreads();
    float S = 0.f, SS = 0.f;
    #pragma unroll
    for (int w = 0; w < 8; w++) { S += sh[0][w]; SS += sh[1][w]; }
    float mu  = S * (1.0f / DM);
    float var = SS * (1.0f / DM) - mu * mu;
    float inv = rsqrtf(var + 1e-5f);
    float pe[NE];
    #pragma unroll
    for (int e = 0; e < NE; e++) pe[e] = 0.f;
    #pragma unroll
    for (int i = 0; i < 4; i++) {
        int idx = tid + i * 256;
        float o = (v[i] - mu) * inv * g[idx] + b[idx];
        oh[(size_t)row * DM + idx] = __float2half_rn(o);
        const float* w = wr + idx * NE;
        #pragma unroll
        for (int e = 0; e < NE; e++) pe[e] += o * w[e];
    }
    __shared__ float red[NE][256];
    #pragma unroll
    for (int e = 0; e < NE; e++) red[e][tid] = pe[e];
    __syncthreads();
    for (int st = 128; st > 0; st >>= 1) {
        if (tid < st) {
            #pragma unroll
            for (int e = 0; e < NE; e++) red[e][tid] += red[e][tid + st];
        }
        __syncthreads();
    }
    if (tid == 0) {
        float lg[NE], mx = -1e30f;
        #pragma unroll
        for (int e = 0; e < NE; e++) { lg[e] = red[e][0]; mx = fmaxf(mx, lg[e]); }
        float se = 0.f, pr[NE];
        #pragma unroll
        for (int e = 0; e < NE; e++) { pr[e] = __expf(lg[e] - mx); se += pr[e]; }
        float invs = 1.0f / se;
        #pragma unroll
        for (int e = 0; e < NE; e++) {
            pr[e] *= invs;
            atomicAdd(&g_probsum[e], pr[e]);
        }
        int i0 = 0;
        #pragma unroll
        for (int e = 1; e < NE; e++) if (pr[e] > pr[i0]) i0 = e;
        int i1 = (i0 == 0) ? 1 : 0;
        #pragma unroll
        for (int e = 0; e < NE; e++) if (e != i0 && pr[e] > pr[i1]) i1 = e;
        float w0 = pr[i0], w1 = pr[i1], sw = 1.0f / (w0 + w1);
        g_top_i[row * 2] = i0; g_top_i[row * 2 + 1] = i1;
        g_top_w[row * 2] = w0 * sw; g_top_w[row * 2 + 1] = w1 * sw;
        atomicAdd(&g_cnt[i0], 1);
        atomicAdd(&g_cnt[i1], 1);
    }
}

// ---------------- tensor-core flash attention --------------------------------
#define ATTN_SMEM 49152
__global__ void __launch_bounds__(256, 2) attn_kernel(
    const h16* __restrict__ q, const h16* __restrict__ k,
    const h16* __restrict__ v, h16* __restrict__ oh)
{
    extern __shared__ char smem[];
    uint32_t sb = smem_u32(smem);
    const uint32_t SQ = 0, SKV = 16384, STG = 16384;

    int bh = blockIdx.x & (NBH - 1);
    int chunk = (TT / 128 - 1) - (blockIdx.x >> 6);
    int qb0 = chunk * 128;
    int tid = threadIdx.x, lane = tid & 31, w = tid >> 5;
    const h16* qb = q + (size_t)bh * TT * HD;
    const h16* kb = k + (size_t)bh * TT * HD;
    const h16* vb = v + (size_t)bh * TT * HD;

    for (int i = tid; i < 128 * 8; i += 256) {
        int r = i >> 3, ch = i & 7;
        uint32_t so = sw128((uint32_t)(r * 128 + ch * 16));
        *(uint4*)(smem + SQ + so) = *(const uint4*)(qb + (size_t)(qb0 + r) * HD + ch * 8);
    }

    auto load_kv = [&](int j0, int st) {
        uint32_t s0 = sb + SKV + (uint32_t)st * STG;
        #pragma unroll
        for (int i = 0; i < 2; i++) {
            int idx = tid + i * 256;
            int r = idx >> 3, ch = idx & 7;
            uint32_t so = sw128((uint32_t)(r * 128 + ch * 16));
            cp_async16(s0 + so, kb + (size_t)(j0 + r) * HD + ch * 8, 16);
            cp_async16(s0 + 8192 + so, vb + (size_t)(j0 + r) * HD + ch * 8, 16);
        }
        cp_commit();
    };
    load_kv(0, 0);
    __syncthreads();

    uint32_t qf[4][4];
    #pragma unroll
    for (int ks = 0; ks < 4; ks++) {
        int row = w * 16 + (lane & 15);
        uint32_t so = sw128((uint32_t)(row * 128 + ks * 32 + (lane >> 4) * 16));
        ldsm4(qf[ks], sb + SQ + so);
    }

    float oacc[8][4];
    #pragma unroll
    for (int i = 0; i < 8; i++)
        #pragma unroll
        for (int j = 0; j < 4; j++) oacc[i][j] = 0.f;
    float mrun[2] = {-1e30f, -1e30f}, lsum[2] = {0.f, 0.f};

    const int wrow = qb0 + w * 16 + (lane >> 2);
    const int wt_last = qb0 + w * 16 + 15;
    const int wt_first = qb0 + w * 16;
    const int ntiles = (qb0 + 128) / 64;

    for (int ti = 0; ti < ntiles; ti++) {
        int j0 = ti * 64;
        if (ti + 1 < ntiles) { load_kv(j0 + 64, (ti + 1) & 1); cp_wait<1>(); }
        else cp_wait<0>();
        __syncthreads();
        if (j0 <= wt_last) {
            uint32_t s0 = sb + SKV + (uint32_t)(ti & 1) * STG;
            float sacc[8][4];
            #pragma unroll
            for (int i = 0; i < 8; i++)
                #pragma unroll
                for (int j = 0; j < 4; j++) sacc[i][j] = 0.f;
            #pragma unroll
            for (int ks = 0; ks < 4; ks++) {
                #pragma unroll
                for (int n2 = 0; n2 < 4; n2++) {
                    int row = n2 * 16 + (lane & 15);
                    uint32_t so = sw128((uint32_t)(row * 128 + ks * 32 + (lane >> 4) * 16));
                    uint32_t t4[4]; ldsm4(t4, s0 + so);
                    uint32_t b0[2] = {t4[0], t4[2]}, b1[2] = {t4[1], t4[3]};
                    mma_f16(sacc[2 * n2], qf[ks], b0);
                    mma_f16(sacc[2 * n2 + 1], qf[ks], b1);
                }
            }
            if (j0 + 63 > wt_first) {
                #pragma unroll
                for (int nt = 0; nt < 8; nt++)
                    #pragma unroll
                    for (int r = 0; r < 4; r++) {
                        int col = j0 + 8 * nt + 2 * (lane & 3) + (r & 1);
                        int rowt = wrow + 8 * (r >> 1);
                        if (col > rowt) sacc[nt][r] = -1e30f;
                    }
            }
            float psc[2];
            #pragma unroll
            for (int hh = 0; hh < 2; hh++) {
                float mx = -1e30f;
                #pragma unroll
                for (int nt = 0; nt < 8; nt++) {
                    mx = fmaxf(mx, sacc[nt][2 * hh]);
                    mx = fmaxf(mx, sacc[nt][2 * hh + 1]);
                }
                mx = fmaxf(mx, __shfl_xor_sync(0xffffffffu, mx, 1));
                mx = fmaxf(mx, __shfl_xor_sync(0xffffffffu, mx, 2));
                float nm = fmaxf(mrun[hh], mx);
                float sc = __expf(mrun[hh] - nm);
                mrun[hh] = nm;
                float sum = 0.f;
                #pragma unroll
                for (int nt = 0; nt < 8; nt++) {
                    float p0 = __expf(sacc[nt][2 * hh] - nm);
                    float p1 = __expf(sacc[nt][2 * hh + 1] - nm);
                    sacc[nt][2 * hh] = p0; sacc[nt][2 * hh + 1] = p1;
                    sum += p0 + p1;
                }
                sum += __shfl_xor_sync(0xffffffffu, sum, 1);
                sum += __shfl_xor_sync(0xffffffffu, sum, 2);
                lsum[hh] = lsum[hh] * sc + sum;
                psc[hh] = sc;
            }
            #pragma unroll
            for (int nt = 0; nt < 8; nt++)
                #pragma unroll
                for (int r = 0; r < 4; r++)
                    oacc[nt][r] *= psc[r >> 1];
            uint32_t pf[4][4];
            #pragma unroll
            for (int kt = 0; kt < 4; kt++) {
                pf[kt][0] = h2pack(sacc[2 * kt][0], sacc[2 * kt][1]);
                pf[kt][1] = h2pack(sacc[2 * kt][2], sacc[2 * kt][3]);
                pf[kt][2] = h2pack(sacc[2 * kt + 1][0], sacc[2 * kt + 1][1]);
                pf[kt][3] = h2pack(sacc[2 * kt + 1][2], sacc[2 * kt + 1][3]);
            }
            uint32_t sv = s0 + 8192;
            int g = lane >> 3, rr = lane & 7;
            #pragma unroll
            for (int dp = 0; dp < 4; dp++) {
                #pragma unroll
                for (int kt = 0; kt < 4; kt++) {
                    int kvr = 16 * kt + 8 * (g & 1) + rr;
                    int dc = dp * 16 + 8 * (g >> 1);
                    uint32_t so = sw128((uint32_t)(kvr * 128 + dc * 2));
                    uint32_t t4[4]; ldsm4t(t4, sv + so);
                    uint32_t b0[2] = {t4[0], t4[1]}, b1[2] = {t4[2], t4[3]};
                    mma_f16(oacc[2 * dp], pf[kt], b0);
                    mma_f16(oacc[2 * dp + 1], pf[kt], b1);
                }
            }
        }
        __syncthreads();
    }
    int b = bh >> 4, hH = bh & 15;
    #pragma unroll
    for (int hh = 0; hh < 2; hh++) {
        float inv = 1.0f / lsum[hh];
        int t = wrow + 8 * hh;
        size_t op = ((size_t)(b * TT + t)) * DM + hH * HD;
        #pragma unroll
        for (int nt = 0; nt < 8; nt++) {
            int d = 8 * nt + 2 * (lane & 3);
            half2 hv = __floats2half2_rn(oacc[nt][2 * hh] * inv, oacc[nt][2 * hh + 1] * inv);
            *(half2*)(oh + op + d) = hv;
        }
    }
}

// ===================== 128x256 HMMA GEMM core (4-stage, occ 1) ===============
#define NSTG 4
__device__ __forceinline__ void gemm256(
    uint32_t sb, float (*acc)[4],
    const h16* __restrict__ A, const h16* __restrict__ B,
    int K, const int* __restrict__ perm, int row_base, int valid, int n0)
{
    constexpr uint32_t T_B = 16384;
    constexpr uint32_t STAGE = 49152;
    const int tid = threadIdx.x, lane = tid & 31, wid = tid >> 5;
    const int wm = wid >> 2, wn = wid & 3;
    const int nkb = K >> 6;

    const int arow = tid >> 3, ach = tid & 7;
    uint32_t asz[4];
    size_t aoff[4];
    #pragma unroll
    for (int it = 0; it < 4; it++) {
        int row = arow + it * 32;
        asz[it] = (row < valid) ? 16u : 0u;
        int gra = (row < valid) ? (perm ? perm[row_base + row] : (row_base + row)) : 0;
        aoff[it] = (size_t)gra * K;
    }

    auto load_stage = [&](int kb) {
        uint32_t s0 = sb + (uint32_t)(kb & (NSTG - 1)) * STAGE;
        int koff = kb * 64 + ach * 8;
        #pragma unroll
        for (int it = 0; it < 4; it++) {
            int row = arow + it * 32;
            uint32_t so = sw128((uint32_t)(row * 128 + ach * 16));
            cp_async16(s0 + so, A + aoff[it] + koff, asz[it]);
        }
        #pragma unroll
        for (int it = 0; it < 8; it++) {
            int row = arow + it * 32;
            uint32_t so = sw128((uint32_t)(row * 128 + ach * 16));
            cp_async16(s0 + T_B + so, B + (size_t)(n0 + row) * K + koff, 16u);
        }
        cp_commit();
    };

    #pragma unroll
    for (int s = 0; s < NSTG - 1; s++)
        if (s < nkb) load_stage(s);

    for (int kb = 0; kb < nkb; kb++) {
        if (kb + NSTG - 1 < nkb) { load_stage(kb + NSTG - 1); cp_wait<NSTG - 1>(); }
        else {
            int rem = nkb - 1 - kb;
            if (rem >= 2) cp_wait<2>();
            else if (rem == 1) cp_wait<1>();
            else cp_wait<0>();
        }
        __syncthreads();
        uint32_t s0 = sb + (uint32_t)(kb & (NSTG - 1)) * STAGE;
        #pragma unroll
        for (int ks = 0; ks < 4; ks++) {
            uint32_t af[4][4];
            #pragma unroll
            for (int mt = 0; mt < 4; mt++) {
                int row = wm * 64 + mt * 16 + (lane & 15);
                uint32_t so = sw128((uint32_t)(row * 128 + ks * 32 + (lane >> 4) * 16));
                ldsm4(af[mt], s0 + so);
            }
            uint32_t bf[8][2];
            #pragma unroll
            for (int n2 = 0; n2 < 4; n2++) {
                int row = wn * 64 + n2 * 16 + (lane & 15);
                uint32_t so = sw128((uint32_t)(row * 128 + ks * 32 + (lane >> 4) * 16));
                uint32_t t4[4];
                ldsm4(t4, s0 + T_B + so);
                bf[n2 * 2][0] = t4[0]; bf[n2 * 2][1] = t4[2];
                bf[n2 * 2 + 1][0] = t4[1]; bf[n2 * 2 + 1][1] = t4[3];
            }
            #pragma unroll
            for (int mt = 0; mt < 4; mt++)
                #pragma unroll
                for (int nt = 0; nt < 8; nt++)
                    mma_f16(acc[mt * 8 + nt], af[mt], bf[nt]);
        }
        __syncthreads();
    }
}
// acc[mt*8+nt][r]: row = wm*64 + mt*16 + lane/4 + 8*(r>>1)
//                  col = wn*64 + nt*8  + 2*(lane&3) + (r&1)

#define GEMM_SMEM 196608
#define ACC_INIT float acc[32][4]; \
    _Pragma("unroll") for (int i = 0; i < 32; i++) \
    _Pragma("unroll") for (int j = 0; j < 4; j++) acc[i][j] = 0.f;

// ---------------- qkv gemm + fused rope -> fp16 q/k/v ------------------------
__global__ void __launch_bounds__(256, 1) qkv_gemm() {
    extern __shared__ char smem[];
    uint32_t sb = smem_u32(smem);
    ACC_INIT
    int m0 = blockIdx.y * 128, n0 = blockIdx.x * 256;
    gemm256(sb, acc, g_xn1_h, g_wqkvt_h, DM, nullptr, m0, 128, n0);
    int lane = threadIdx.x & 31, wid = threadIdx.x >> 5;
    int wm = wid >> 2, wn = wid & 3;
    int c_base = n0 + wn * 64;
    int sec = c_base >> 10;             // 0=q, 1=k, 2=v
    int h = (c_base & 1023) >> 6;       // head index
    h16* dstq = (sec == 0) ? g_qh : g_kh;
    #pragma unroll
    for (int mt = 0; mt < 4; mt++) {
        #pragma unroll
        for (int half = 0; half < 2; half++) {
            int rg = m0 + wm * 64 + mt * 16 + (lane >> 2) + half * 8;
            int t = rg & (TT - 1), bb = rg >> 10;
            size_t dbase = ((size_t)((bb * NH + h) * TT) + t) * HD;
            #pragma unroll
            for (int nt = 0; nt < 4; nt++) {
                int d = nt * 8 + 2 * (lane & 3);
                float a0 = acc[mt * 8 + nt][half * 2];
                float a1 = acc[mt * 8 + nt][half * 2 + 1];
                float b0 = acc[mt * 8 + nt + 4][half * 2];
                float b1 = acc[mt * 8 + nt + 4][half * 2 + 1];
                if (sec == 2) {
                    *(half2*)(g_vh + dbase + d)      = __floats2half2_rn(a0, a1);
                    *(half2*)(g_vh + dbase + d + 32) = __floats2half2_rn(b0, b1);
                } else {
                    float2 cs0 = g_rope_tab[t * 32 + d];
                    float2 cs1 = g_rope_tab[t * 32 + d + 1];
                    float lo0 = a0 * cs0.x - b0 * cs0.y;
                    float lo1 = a1 * cs1.x - b1 * cs1.y;
                    float hi0 = b0 * cs0.x + a0 * cs0.y;
                    float hi1 = b1 * cs1.x + a1 * cs1.y;
                    if (sec == 0) { lo0 *= 0.125f; lo1 *= 0.125f; hi0 *= 0.125f; hi1 *= 0.125f; }
                    *(half2*)(dstq + dbase + d)      = __floats2half2_rn(lo0, lo1);
                    *(half2*)(dstq + dbase + d + 32) = __floats2half2_rn(hi0, hi1);
                }
            }
        }
    }
}

// ---------------- x2 = attn @ w_proj + b_proj + x -> out ---------------------
__global__ void __launch_bounds__(256, 1) proj_gemm(
    const float* __restrict__ bias, const float* __restrict__ resid,
    float* __restrict__ out)
{
    extern __shared__ char smem[];
    uint32_t sb = smem_u32(smem);
    ACC_INIT
    int m0 = blockIdx.y * 128, n0 = blockIdx.x * 256;
    gemm256(sb, acc, g_attn_h, g_wprojt_h, DM, nullptr, m0, 128, n0);
    int lane = threadIdx.x & 31, wid = threadIdx.x >> 5;
    int wm = wid >> 2, wn = wid & 3;
    #pragma unroll
    for (int mt = 0; mt < 4; mt++)
        #pragma unroll
        for (int nt = 0; nt < 8; nt++) {
            int r = m0 + wm * 64 + mt * 16 + (lane >> 2);
            int c = n0 + wn * 64 + nt * 8 + 2 * (lane & 3);
            float* d = acc[mt * 8 + nt];
            size_t p0 = (size_t)r * DM + c;
            size_t p1 = (size_t)(r + 8) * DM + c;
            out[p0]     = d[0] + bias[c]     + resid[p0];
            out[p0 + 1] = d[1] + bias[c + 1] + resid[p0 + 1];
            out[p1]     = d[2] + bias[c]     + resid[p1];
            out[p1 + 1] = d[3] + bias[c + 1] + resid[p1 + 1];
        }
}

// ---------------- h = gelu(gather(xn2) @ w1[e] + b1[e]) ----------------------
__global__ void __launch_bounds__(256, 1) ffn1_gemm(const float* __restrict__ B1) {
    int e = blockIdx.z;
    int cnt = g_cnt[e];
    int r0 = blockIdx.y * 128;
    if (r0 >= cnt) return;
    extern __shared__ char smem[];
    uint32_t sb = smem_u32(smem);
    ACC_INIT
    int off = g_off[e];
    int n0 = blockIdx.x * 256;
    int valid = cnt - r0; if (valid > 128) valid = 128;
    gemm256(sb, acc, g_xn2_h, g_w1t + (size_t)e * DFF * DM,
            DM, g_perm_tok, off + r0, valid, n0);
    int lane = threadIdx.x & 31, wid = threadIdx.x >> 5;
    int wm = wid >> 2, wn = wid & 3;
    const float* bias = B1 + e * DFF;
    #pragma unroll
    for (int mt = 0; mt < 4; mt++)
        #pragma unroll
        for (int nt = 0; nt < 8; nt++) {
            int rl = wm * 64 + mt * 16 + (lane >> 2);
            int c = n0 + wn * 64 + nt * 8 + 2 * (lane & 3);
            float* d = acc[mt * 8 + nt];
            #pragma unroll
            for (int half = 0; half < 2; half++) {
                int row = rl + half * 8;
                if (row >= valid) continue;
                size_t rp = (size_t)(off + r0 + row) * DFF + c;
                #pragma unroll
                for (int u = 0; u < 2; u++) {
                    float v = d[half * 2 + u] + bias[c + u];
                    v = 0.5f * v * (1.0f + erff(v * 0.70710678118654752f));
                    g_hbuf[rp + u] = __float2half_rn(v);
                }
            }
        }
}

// ---------------- out += gate * (h @ w2[e] + b2[e]) (fused combine) ----------
__global__ void __launch_bounds__(256, 1) ffn2_gemm(
    const float* __restrict__ B2, float* __restrict__ out)
{
    int e = blockIdx.z;
    int cnt = g_cnt[e];
    int r0 = blockIdx.y * 128;
    if (r0 >= cnt) return;
    extern __shared__ char smem[];
    uint32_t sb = smem_u32(smem);
    ACC_INIT
    int off = g_off[e];
    int n0 = blockIdx.x * 256;
    int valid = cnt - r0; if (valid > 128) valid = 128;
    gemm256(sb, acc, g_hbuf, g_w2t + (size_t)e * DM * DFF,
            DFF, nullptr, off + r0, valid, n0);
    int lane = threadIdx.x & 31, wid = threadIdx.x >> 5;
    int wm = wid >> 2, wn = wid & 3;
    const float* bias = B2 + e * DM;
    #pragma unroll
    for (int mt = 0; mt < 4; mt++) {
        #pragma unroll
        for (int half = 0; half < 2; half++) {
            int row = wm * 64 + mt * 16 + (lane >> 2) + half * 8;
            if (row >= valid) continue;
            int slot = off + r0 + row;
            int tok = g_perm_tok[slot];
            float gate = g_slot_gate[slot];
            float* orow = out + (size_t)tok * DM;
            #pragma unroll
            for (int nt = 0; nt < 8; nt++) {
                int c = n0 + wn * 64 + nt * 8 + 2 * (lane & 3);
                float* d = acc[mt * 8 + nt];
                atomicAdd(orow + c,     gate * (d[half * 2]     + bias[c]));
                atomicAdd(orow + c + 1, gate * (d[half * 2 + 1] + bias[c + 1]));
            }
        }
    }
}

__global__ void scan_kernel(float* __restrict__ out, int out_size) {
    if (threadIdx.x == 0 && blockIdx.x == 0) {
        int o = 0;
        float aux = 0.f;
        for (int e = 0; e < NE; e++) { g_off[e] = o; o += g_cnt[e]; }
        for (int e = 0; e < NE; e++)
            aux += ((float)g_cnt[e] / (float)(NTOK * 2)) * (g_probsum[e] / (float)NTOK);
        if (out_size > NTOK * DM) out[NTOK * DM] = (float)NE * aux;
    }
}

__global__ void place_kernel() {
    int s = blockIdx.x * 256 + threadIdx.x;
    if (s >= NSLOT) return;
    int tok = s >> 1;
    int e = g_top_i[s];
    float w = g_top_w[s];
    int pos = atomicAdd(&g_cur[e], 1);
    int slot = g_off[e] + pos;
    g_perm_tok[slot] = tok;
    g_slot_gate[slot] = w;
}

// ===================== launch =====================
extern "C" void kernel_launch(void* const* d_in, const int* in_sizes, int n_in,
                              void* d_out, int out_size)
{
    const float* x        = (const float*)d_in[0];
    const float* ln1_g    = (const float*)d_in[2];
    const float* ln1_b    = (const float*)d_in[3];
    const float* w_qkv    = (const float*)d_in[4];
    const float* w_proj   = (const float*)d_in[5];
    const float* b_proj   = (const float*)d_in[6];
    const float* ln2_g    = (const float*)d_in[7];
    const float* ln2_b    = (const float*)d_in[8];
    const float* w_router = (const float*)d_in[9];
    const float* w1       = (const float*)d_in[10];
    const float* b1       = (const float*)d_in[11];
    const float* w2       = (const float*)d_in[12];
    const float* b2       = (const float*)d_in[13];
    float* out = (float*)d_out;

    static cudaStream_t s_side = nullptr;
    static cudaEvent_t ev_fork = nullptr, ev_join = nullptr, ev_proj = nullptr;
    static bool attr_done = false;
    if (!attr_done) {
        cudaFuncSetAttribute(qkv_gemm,  cudaFuncAttributeMaxDynamicSharedMemorySize, GEMM_SMEM);
        cudaFuncSetAttribute(proj_gemm, cudaFuncAttributeMaxDynamicSharedMemorySize, GEMM_SMEM);
        cudaFuncSetAttribute(ffn1_gemm, cudaFuncAttributeMaxDynamicSharedMemorySize, GEMM_SMEM);
        cudaFuncSetAttribute(ffn2_gemm, cudaFuncAttributeMaxDynamicSharedMemorySize, GEMM_SMEM);
        cudaFuncSetAttribute(attn_kernel, cudaFuncAttributeMaxDynamicSharedMemorySize, ATTN_SMEM);
        cudaStreamCreateWithFlags(&s_side, cudaStreamNonBlocking);
        cudaEventCreateWithFlags(&ev_fork, cudaEventDisableTiming);
        cudaEventCreateWithFlags(&ev_join, cudaEventDisableTiming);
        cudaEventCreateWithFlags(&ev_proj, cudaEventDisableTiming);
        attr_done = true;
    }

    h16 *p_qh, *p_kh, *p_vh;
    h16 *p_xn1_h, *p_attn_h, *p_xn2_h;
    h16 *p_wqkvt_h, *p_wprojt_h, *p_w1t, *p_w2t;
    cudaGetSymbolAddress((void**)&p_qh,   g_qh);
    cudaGetSymbolAddress((void**)&p_kh,   g_kh);
    cudaGetSymbolAddress((void**)&p_vh,   g_vh);
    cudaGetSymbolAddress((void**)&p_xn1_h, g_xn1_h);
    cudaGetSymbolAddress((void**)&p_attn_h, g_attn_h);
    cudaGetSymbolAddress((void**)&p_xn2_h, g_xn2_h);
    cudaGetSymbolAddress((void**)&p_wqkvt_h, g_wqkvt_h);
    cudaGetSymbolAddress((void**)&p_wprojt_h, g_wprojt_h);
    cudaGetSymbolAddress((void**)&p_w1t, g_w1t);
    cudaGetSymbolAddress((void**)&p_w2t, g_w2t);

    zero_small_kernel<<<1, 32>>>();
    rope_tab_kernel<<<TT * 32 / 256, 256>>>();

    // fork: w_proj + FFN weight conversion on side stream (overlap attention chain)
    cudaEventRecord(ev_fork, 0);
    cudaStreamWaitEvent(s_side, ev_fork, 0);
    trans_conv<<<dim3(DM / 32, DM / 32, 1), 256, 0, s_side>>>(w_proj, p_wprojt_h, DM, DM);
    cudaEventRecord(ev_proj, s_side);
    trans_conv<<<dim3(DFF / 32, DM / 32, NE), 256, 0, s_side>>>(w1, p_w1t, DM, DFF);
    trans_conv<<<dim3(DM / 32, DFF / 32, NE), 256, 0, s_side>>>(w2, p_w2t, DFF, DM);
    cudaEventRecord(ev_join, s_side);

    // main chain
    trans_conv<<<dim3(3 * DM / 32, DM / 32, 1), 256>>>(w_qkv, p_wqkvt_h, DM, 3 * DM);
    ln_kernel<<<NTOK, 256>>>(x, ln1_g, ln1_b, p_xn1_h);
    qkv_gemm<<<dim3(3 * DM / 256, NTOK / 128), 256, GEMM_SMEM>>>();   // + fused rope
    attn_kernel<<<NBH * (TT / 128), 256, ATTN_SMEM>>>(p_qh, p_kh, p_vh, p_attn_h);
    cudaStreamWaitEvent(0, ev_proj, 0);
    proj_gemm<<<dim3(DM / 256, NTOK / 128), 256, GEMM_SMEM>>>(b_proj, x, out);
    ln2_router_kernel<<<NTOK, 256>>>(out, ln2_g, ln2_b, p_xn2_h, w_router);
    scan_kernel<<<1, 1>>>(out, out_size);
    place_kernel<<<NSLOT / 256, 256>>>();

    // join before expert GEMMs. y-grid = NTOK/128 = 32 (per-expert cnt <= NTOK,
    // since each token routes to two DISTINCT experts).
    cudaStreamWaitEvent(0, ev_join, 0);
    ffn1_gemm<<<dim3(DFF / 256, NTOK / 128, NE), 256, GEMM_SMEM>>>(b1);
    ffn2_gemm<<<dim3(DM / 256, NTOK / 128, NE), 256, GEMM_SMEM>>>(b2, out);
}